// round 1
// baseline (speedup 1.0000x reference)
#include <cuda_runtime.h>
#include <cuda_bf16.h>
#include <math.h>

#define Nn   50000
#define Ee   800000
#define ETOT (Ee + Nn)     // 850000
#define DD   256
#define HH   4
#define NEG  0.2f

// ---- output layout (tuple flatten: node_preds, edge_preds, h, attn_weights) ----
#define NP_OFF  0
#define EP_OFF  (Nn)                    // 50000
#define H_OFF   (Nn + 3*Ee)             // 2450000
#define AT_OFF  (H_OFF + Nn*DD)         // 15250000

// ---- scratch (device globals; no allocation allowed) ----
__device__ float    g_xw [Nn * DD];       // X@W of current layer
__device__ float    g_h1 [Nn * DD];       // elu output of layer 1
__device__ float    g_agg[Nn * DD];       // aggregation buffer (layer 1)
__device__ float    g_Y  [(size_t)Nn * 768]; // bilinear left factors [N,3,256]
__device__ float    g_ss [Nn * HH];
__device__ float    g_sd [Nn * HH];
__device__ unsigned g_menc[Nn * HH];
__device__ float    g_den [Nn * HH];
__device__ float    g_ex  [ETOT * HH];
__device__ int      g_r[ETOT];
__device__ int      g_c[ETOT];
__device__ int      g_is64;

// ============================ helpers ============================
__device__ __forceinline__ unsigned fenc(float f) {
    unsigned u = __float_as_uint(f);
    return (u & 0x80000000u) ? ~u : (u | 0x80000000u);
}
__device__ __forceinline__ float fdec(unsigned u) {
    u = (u & 0x80000000u) ? (u & 0x7fffffffu) : ~u;
    return __uint_as_float(u);
}
__device__ __forceinline__ float lrelu(float x) { return x > 0.f ? x : NEG * x; }

__device__ __forceinline__ void red4(float* p, float4 v) {
    asm volatile("red.global.add.v4.f32 [%0], {%1,%2,%3,%4};"
                 :: "l"(p), "f"(v.x), "f"(v.y), "f"(v.z), "f"(v.w) : "memory");
}

// ============================ index conversion ============================
__global__ void detect_dtype_kernel(const long long* p) {
    if (blockIdx.x == 0 && threadIdx.x == 0) {
        int ok = 1;
        for (int i = 0; i < 64; i++) {
            long long v = p[i];
            if (v < 0 || v >= Nn) { ok = 0; break; }
        }
        g_is64 = ok;   // 1 => data really is int64
    }
}

__global__ void conv_idx_kernel(const void* pv, int* r, int* c) {
    int e = blockIdx.x * blockDim.x + threadIdx.x;
    if (e >= ETOT) return;
    if (e >= Ee) { r[e] = e - Ee; c[e] = e - Ee; return; }
    if (g_is64) {
        const long long* p = (const long long*)pv;
        r[e] = (int)p[e]; c[e] = (int)p[Ee + e];
    } else {
        const int* p = (const int*)pv;
        r[e] = p[e]; c[e] = p[Ee + e];
    }
}

// ============================ GEMM: C[M,N] = A[M,K] @ B[K,N] ============================
#define GBM 128
#define GBN 128
#define GBK 16

__global__ __launch_bounds__(256) void gemm_f32(
    const float* __restrict__ A, const float* __restrict__ B,
    float* __restrict__ C, int M, int N, int K, int ldc)
{
    __shared__ float As[GBK][GBM + 4];
    __shared__ float Bs[GBK][GBN];
    const int bm = blockIdx.y * GBM;
    const int bn = blockIdx.x * GBN;
    const int tid = threadIdx.x;
    const int tx = tid & 15, ty = tid >> 4;

    float acc[8][8];
#pragma unroll
    for (int i = 0; i < 8; i++)
#pragma unroll
        for (int j = 0; j < 8; j++) acc[i][j] = 0.f;

    for (int k0 = 0; k0 < K; k0 += GBK) {
        // A tile: 128 rows x 16 cols (transposed into As)
#pragma unroll
        for (int it = 0; it < 2; it++) {
            int f4 = tid + it * 256;       // 0..511
            int row = f4 >> 2;             // 0..127
            int c4  = f4 & 3;              // 0..3
            float4 v = make_float4(0.f, 0.f, 0.f, 0.f);
            int grow = bm + row;
            if (grow < M) v = *(const float4*)(A + (size_t)grow * K + k0 + c4 * 4);
            As[c4*4+0][row] = v.x; As[c4*4+1][row] = v.y;
            As[c4*4+2][row] = v.z; As[c4*4+3][row] = v.w;
        }
        // B tile: 16 rows x 128 cols
#pragma unroll
        for (int it = 0; it < 2; it++) {
            int f4 = tid + it * 256;
            int row = f4 >> 5;             // 0..15
            int c4  = f4 & 31;             // 0..31
            float4 v = *(const float4*)(B + (size_t)(k0 + row) * N + bn + c4 * 4);
            *(float4*)&Bs[row][c4 * 4] = v;
        }
        __syncthreads();
#pragma unroll
        for (int k = 0; k < GBK; k++) {
            float4 a0 = *(const float4*)&As[k][ty * 8];
            float4 a1 = *(const float4*)&As[k][ty * 8 + 4];
            float4 b0 = *(const float4*)&Bs[k][tx * 8];
            float4 b1 = *(const float4*)&Bs[k][tx * 8 + 4];
            float a[8] = {a0.x, a0.y, a0.z, a0.w, a1.x, a1.y, a1.z, a1.w};
            float b[8] = {b0.x, b0.y, b0.z, b0.w, b1.x, b1.y, b1.z, b1.w};
#pragma unroll
            for (int i = 0; i < 8; i++)
#pragma unroll
                for (int j = 0; j < 8; j++) acc[i][j] += a[i] * b[j];
        }
        __syncthreads();
    }
#pragma unroll
    for (int i = 0; i < 8; i++) {
        int grow = bm + ty * 8 + i;
        if (grow < M) {
            float* cp = C + (size_t)grow * ldc + bn + tx * 8;
            *(float4*)(cp + 0) = make_float4(acc[i][0], acc[i][1], acc[i][2], acc[i][3]);
            *(float4*)(cp + 4) = make_float4(acc[i][4], acc[i][5], acc[i][6], acc[i][7]);
        }
    }
}

// ============================ attention scores ============================
// s_src[n,h] = dot(xw[n, h*64:(h+1)*64], a_src[h]); same for dst. Warp per node.
__global__ void scores_kernel(const float* __restrict__ xw,
                              const float* __restrict__ a_src,
                              const float* __restrict__ a_dst,
                              float* __restrict__ s_src,
                              float* __restrict__ s_dst)
{
    int w = (blockIdx.x * blockDim.x + threadIdx.x) >> 5;
    int lane = threadIdx.x & 31;
    if (w >= Nn) return;
    const float4* xp  = (const float4*)(xw + (size_t)w * DD);
    const float4* asp = (const float4*)a_src;
    const float4* adp = (const float4*)a_dst;
    float ps = 0.f, pd = 0.f;
#pragma unroll
    for (int q = 0; q < 2; q++) {
        int i = lane * 2 + q;
        float4 x4 = xp[i];
        float4 s4 = asp[i], d4 = adp[i];
        ps += x4.x * s4.x + x4.y * s4.y + x4.z * s4.z + x4.w * s4.w;
        pd += x4.x * d4.x + x4.y * d4.y + x4.z * d4.z + x4.w * d4.w;
    }
    // lane covers floats [lane*8, lane*8+8) -> single head = lane>>3; reduce groups of 8
#pragma unroll
    for (int off = 4; off; off >>= 1) {
        ps += __shfl_down_sync(0xffffffffu, ps, off);
        pd += __shfl_down_sync(0xffffffffu, pd, off);
    }
    if ((lane & 7) == 0) {
        int h = lane >> 3;
        s_src[w * HH + h] = ps;
        s_dst[w * HH + h] = pd;
    }
}

// ============================ softmax passes ============================
__global__ void zero_md_kernel(unsigned* menc, float* den) {
    int i = blockIdx.x * blockDim.x + threadIdx.x;
    if (i < Nn * HH) { menc[i] = 0u; den[i] = 0.f; }
}

__global__ void pass_max_kernel(const float* __restrict__ s_src,
                                const float* __restrict__ s_dst,
                                const int* __restrict__ r, const int* __restrict__ c,
                                float* __restrict__ ex, unsigned* __restrict__ menc)
{
    int e = blockIdx.x * blockDim.x + threadIdx.x;
    if (e >= ETOT) return;
    int ri = r[e], ci = c[e];
    float4 ss = *(const float4*)(s_src + ri * HH);
    float4 sd = *(const float4*)(s_dst + ci * HH);
    float4 l = make_float4(lrelu(ss.x + sd.x), lrelu(ss.y + sd.y),
                           lrelu(ss.z + sd.z), lrelu(ss.w + sd.w));
    *(float4*)(ex + (size_t)e * HH) = l;
    atomicMax(&menc[ci * HH + 0], fenc(l.x));
    atomicMax(&menc[ci * HH + 1], fenc(l.y));
    atomicMax(&menc[ci * HH + 2], fenc(l.z));
    atomicMax(&menc[ci * HH + 3], fenc(l.w));
}

__global__ void pass_exp_kernel(const int* __restrict__ c,
                                const unsigned* __restrict__ menc,
                                float* __restrict__ ex, float* __restrict__ den)
{
    int e = blockIdx.x * blockDim.x + threadIdx.x;
    if (e >= ETOT) return;
    int ci = c[e];
    float4 l = *(const float4*)(ex + (size_t)e * HH);
    uint4 m = *(const uint4*)(menc + ci * HH);
    float4 v = make_float4(__expf(l.x - fdec(m.x)), __expf(l.y - fdec(m.y)),
                           __expf(l.z - fdec(m.z)), __expf(l.w - fdec(m.w)));
    // use accurate expf for safety against rel_err
    v = make_float4(expf(l.x - fdec(m.x)), expf(l.y - fdec(m.y)),
                    expf(l.z - fdec(m.z)), expf(l.w - fdec(m.w)));
    *(float4*)(ex + (size_t)e * HH) = v;
    red4(den + ci * HH, v);
}

__global__ void bias_init_kernel(float* __restrict__ out, const float* __restrict__ b) {
    int i = blockIdx.x * blockDim.x + threadIdx.x;
    if (i < Nn * DD) out[i] = b[i & (DD - 1)];
}

// warp per edge: out[c] += alpha_h * xw[r]; also attn accumulation
__global__ void aggregate_kernel(const int* __restrict__ r, const int* __restrict__ c,
                                 const float* __restrict__ ex, const float* __restrict__ den,
                                 const float* __restrict__ xw, float* __restrict__ out,
                                 float* __restrict__ attn, int accumulate)
{
    int e = (blockIdx.x * blockDim.x + threadIdx.x) >> 5;
    int lane = threadIdx.x & 31;
    if (e >= ETOT) return;
    int ri = r[e], ci = c[e];
    int h = lane >> 3;                       // lane covers floats [lane*8, lane*8+8)
    float alpha = ex[(size_t)e * HH + h] / den[ci * HH + h];
    const float4* xp = (const float4*)(xw + (size_t)ri * DD);
    float* op = out + (size_t)ci * DD;
#pragma unroll
    for (int q = 0; q < 2; q++) {
        int i = lane * 2 + q;
        float4 v = xp[i];
        v.x *= alpha; v.y *= alpha; v.z *= alpha; v.w *= alpha;
        red4(op + i * 4, v);
    }
    if (lane == 0) {
        float4 e4 = *(const float4*)(ex + (size_t)e * HH);
        float4 d4 = *(const float4*)(den + ci * HH);
        float s = 0.125f * (e4.x / d4.x + e4.y / d4.y + e4.z / d4.z + e4.w / d4.w);
        if (accumulate) attn[e] += s; else attn[e] = s;
    }
}

__global__ void elu_kernel(const float* __restrict__ in, float* __restrict__ out, int n) {
    int i = blockIdx.x * blockDim.x + threadIdx.x;
    if (i < n) {
        float v = in[i];
        out[i] = v > 0.f ? v : (expf(v) - 1.f);
    }
}

// ============================ prediction heads ============================
__global__ void node_pred_kernel(const float* __restrict__ h, const float* __restrict__ Wn,
                                 const float* __restrict__ bn, float* __restrict__ out)
{
    int n = (blockIdx.x * blockDim.x + threadIdx.x) >> 5;
    int lane = threadIdx.x & 31;
    if (n >= Nn) return;
    const float4* hp = (const float4*)(h + (size_t)n * DD);
    const float4* wp = (const float4*)Wn;
    float s = 0.f;
#pragma unroll
    for (int q = 0; q < 2; q++) {
        int i = lane * 2 + q;
        float4 a = hp[i], b = wp[i];
        s += a.x * b.x + a.y * b.y + a.z * b.z + a.w * b.w;
    }
#pragma unroll
    for (int off = 16; off; off >>= 1) s += __shfl_down_sync(0xffffffffu, s, off);
    if (lane == 0) out[n] = s + bn[0];
}

// warp per (original) edge: ep[e,o] = dot(Y[r, o, :], h[c, :]) + bb[o]
__global__ void edge_pred_kernel(const int* __restrict__ r, const int* __restrict__ c,
                                 const float* __restrict__ h, const float* __restrict__ Y,
                                 const float* __restrict__ bb, float* __restrict__ out)
{
    int e = (blockIdx.x * blockDim.x + threadIdx.x) >> 5;
    int lane = threadIdx.x & 31;
    if (e >= Ee) return;
    int ri = r[e], ci = c[e];
    const float4* hp = (const float4*)(h + (size_t)ci * DD);
    float4 h0 = hp[lane * 2], h1 = hp[lane * 2 + 1];
    float s[3];
#pragma unroll
    for (int o = 0; o < 3; o++) {
        const float4* yp = (const float4*)(Y + (size_t)ri * 768 + o * DD);
        float4 y0 = yp[lane * 2], y1 = yp[lane * 2 + 1];
        s[o] = h0.x * y0.x + h0.y * y0.y + h0.z * y0.z + h0.w * y0.w
             + h1.x * y1.x + h1.y * y1.y + h1.z * y1.z + h1.w * y1.w;
    }
#pragma unroll
    for (int off = 16; off; off >>= 1) {
#pragma unroll
        for (int o = 0; o < 3; o++) s[o] += __shfl_down_sync(0xffffffffu, s[o], off);
    }
    if (lane == 0) {
        out[(size_t)e * 3 + 0] = s[0] + bb[0];
        out[(size_t)e * 3 + 1] = s[1] + bb[1];
        out[(size_t)e * 3 + 2] = s[2] + bb[2];
    }
}

// ============================ host launch ============================
extern "C" void kernel_launch(void* const* d_in, const int* in_sizes, int n_in,
                              void* d_out, int out_size)
{
    const float*     x   = (const float*)d_in[0];
    const void*      ei  = d_in[1];
    const float*     W1  = (const float*)d_in[2];
    const float*     a1s = (const float*)d_in[3];
    const float*     a1d = (const float*)d_in[4];
    const float*     b1  = (const float*)d_in[5];
    const float*     W2  = (const float*)d_in[6];
    const float*     a2s = (const float*)d_in[7];
    const float*     a2d = (const float*)d_in[8];
    const float*     b2  = (const float*)d_in[9];
    const float*     Wn  = (const float*)d_in[10];
    const float*     bn  = (const float*)d_in[11];
    const float*     Wb  = (const float*)d_in[12];
    const float*     bb  = (const float*)d_in[13];
    float* out = (float*)d_out;

    float *xw, *h1, *agg, *Y, *ss, *sd, *den, *ex;
    unsigned* menc; int *r, *c;
    cudaGetSymbolAddress((void**)&xw,   g_xw);
    cudaGetSymbolAddress((void**)&h1,   g_h1);
    cudaGetSymbolAddress((void**)&agg,  g_agg);
    cudaGetSymbolAddress((void**)&Y,    g_Y);
    cudaGetSymbolAddress((void**)&ss,   g_ss);
    cudaGetSymbolAddress((void**)&sd,   g_sd);
    cudaGetSymbolAddress((void**)&menc, g_menc);
    cudaGetSymbolAddress((void**)&den,  g_den);
    cudaGetSymbolAddress((void**)&ex,   g_ex);
    cudaGetSymbolAddress((void**)&r,    g_r);
    cudaGetSymbolAddress((void**)&c,    g_c);

    float* hfin = out + H_OFF;
    float* attn = out + AT_OFF;

    const int TB = 256;
    dim3 gemm_grid((DD + GBN - 1) / GBN, (Nn + GBM - 1) / GBM);   // (2, 391)
    int eb    = (ETOT + TB - 1) / TB;           // 1-thread-per-edge blocks
    int ewb   = (ETOT + 7) / 8;                 // warp-per-edge blocks (8 warps/block)
    int nwb   = (Nn + 7) / 8;                   // warp-per-node blocks
    int ndb   = (Nn * DD + TB - 1) / TB;
    int mdb   = (Nn * HH + TB - 1) / TB;

    detect_dtype_kernel<<<1, 32>>>((const long long*)ei);
    conv_idx_kernel<<<eb, TB>>>(ei, r, c);

    // ---------- layer 1 ----------
    gemm_f32<<<gemm_grid, TB>>>(x, W1, xw, Nn, DD, DD, DD);
    scores_kernel<<<nwb, TB>>>(xw, a1s, a1d, ss, sd);
    zero_md_kernel<<<mdb, TB>>>(menc, den);
    pass_max_kernel<<<eb, TB>>>(ss, sd, r, c, ex, menc);
    pass_exp_kernel<<<eb, TB>>>(c, menc, ex, den);
    bias_init_kernel<<<ndb, TB>>>(agg, b1);
    aggregate_kernel<<<ewb, TB>>>(r, c, ex, den, xw, agg, attn, 0);
    elu_kernel<<<ndb, TB>>>(agg, h1, Nn * DD);

    // ---------- layer 2 ----------
    gemm_f32<<<gemm_grid, TB>>>(h1, W2, xw, Nn, DD, DD, DD);
    scores_kernel<<<nwb, TB>>>(xw, a2s, a2d, ss, sd);
    zero_md_kernel<<<mdb, TB>>>(menc, den);
    pass_max_kernel<<<eb, TB>>>(ss, sd, r, c, ex, menc);
    pass_exp_kernel<<<eb, TB>>>(c, menc, ex, den);
    bias_init_kernel<<<ndb, TB>>>(hfin, b2);
    aggregate_kernel<<<ewb, TB>>>(r, c, ex, den, xw, hfin, attn, 1);
    elu_kernel<<<ndb, TB>>>(hfin, hfin, Nn * DD);

    // ---------- heads ----------
    node_pred_kernel<<<nwb, TB>>>(hfin, Wn, bn, out + NP_OFF);
    for (int o = 0; o < 3; o++)
        gemm_f32<<<gemm_grid, TB>>>(hfin, Wb + (size_t)o * DD * DD, Y + o * DD,
                                    Nn, DD, DD, 768);
    edge_pred_kernel<<<(Ee + 7) / 8, TB>>>(r, c, hfin, Y, bb, out + EP_OFF);
}

// round 2
// speedup vs baseline: 1.1688x; 1.1688x over previous
#include <cuda_runtime.h>
#include <cuda_bf16.h>
#include <math.h>

#define Nn   50000
#define Ee   800000
#define ETOT (Ee + Nn)     // 850000
#define DD   256
#define HH   4
#define NEG  0.2f

// ---- output layout (tuple flatten: node_preds, edge_preds, h, attn_weights) ----
#define NP_OFF  0
#define EP_OFF  (Nn)                    // 50000
#define H_OFF   (Nn + 3*Ee)             // 2450000
#define AT_OFF  (H_OFF + Nn*DD)         // 15250000

// ---- scratch (device globals; no allocation allowed) ----
__device__ float    g_xw [Nn * DD];       // X@W of current layer
__device__ float    g_h1 [Nn * DD];       // elu output of layer 1
__device__ float    g_agg[Nn * DD];       // aggregation buffer (layer 1)
__device__ float    g_Y  [(size_t)Nn * 768]; // bilinear left factors [N,3,256]
__device__ float    g_ss [Nn * HH];
__device__ float    g_sd [Nn * HH];
__device__ unsigned g_menc[Nn * HH];
__device__ float    g_den [Nn * HH];
__device__ float    g_ex  [ETOT * HH];
__device__ int      g_r[ETOT];
__device__ int      g_c[ETOT];
__device__ int      g_is64;

// ============================ helpers ============================
__device__ __forceinline__ unsigned fenc(float f) {
    unsigned u = __float_as_uint(f);
    return (u & 0x80000000u) ? ~u : (u | 0x80000000u);
}
__device__ __forceinline__ float fdec(unsigned u) {
    u = (u & 0x80000000u) ? (u & 0x7fffffffu) : ~u;
    return __uint_as_float(u);
}
__device__ __forceinline__ float lrelu(float x) { return x > 0.f ? x : NEG * x; }

__device__ __forceinline__ void red4(float* p, float4 v) {
    asm volatile("red.global.add.v4.f32 [%0], {%1,%2,%3,%4};"
                 :: "l"(p), "f"(v.x), "f"(v.y), "f"(v.z), "f"(v.w) : "memory");
}

// split fp32 -> tf32 hi + residual lo (3xTF32 trick)
__device__ __forceinline__ void split_tf(float v, unsigned& hi, unsigned& lo) {
    asm("cvt.rna.tf32.f32 %0, %1;" : "=r"(hi) : "f"(v));
    lo = __float_as_uint(v - __uint_as_float(hi));
}

__device__ __forceinline__ void mma8(float* c, const unsigned* a, const unsigned* b) {
    asm volatile(
        "mma.sync.aligned.m16n8k8.row.col.f32.tf32.tf32.f32 "
        "{%0,%1,%2,%3}, {%4,%5,%6,%7}, {%8,%9}, {%0,%1,%2,%3};"
        : "+f"(c[0]), "+f"(c[1]), "+f"(c[2]), "+f"(c[3])
        : "r"(a[0]), "r"(a[1]), "r"(a[2]), "r"(a[3]), "r"(b[0]), "r"(b[1]));
}

// ============================ index conversion ============================
__global__ void detect_dtype_kernel(const long long* p) {
    if (blockIdx.x == 0 && threadIdx.x == 0) {
        int ok = 1;
        for (int i = 0; i < 64; i++) {
            long long v = p[i];
            if (v < 0 || v >= Nn) { ok = 0; break; }
        }
        g_is64 = ok;
    }
}

__global__ void conv_idx_kernel(const void* pv, int* r, int* c) {
    int e = blockIdx.x * blockDim.x + threadIdx.x;
    if (e >= ETOT) return;
    if (e >= Ee) { r[e] = e - Ee; c[e] = e - Ee; return; }
    if (g_is64) {
        const long long* p = (const long long*)pv;
        r[e] = (int)p[e]; c[e] = (int)p[Ee + e];
    } else {
        const int* p = (const int*)pv;
        r[e] = p[e]; c[e] = p[Ee + e];
    }
}

// ============================ 3xTF32 tensor-core GEMM ============================
// C[M, 256] = A[M, 256] @ B[256, 256]; C has stride ldc (col offset baked into C).
// Block tile 128x256, 8 warps, warp tile 64x64, BK=8, double-buffered smem.
#define ASTR 136   // 128 + 8  -> frag-load bank = 8t+g (conflict-free)
#define BSTR 264   // 256 + 8

__global__ __launch_bounds__(256, 1) void gemm_tf32(
    const float* __restrict__ A, const float* __restrict__ B,
    float* __restrict__ C, int M, int ldc)
{
    __shared__ float As[2][8][ASTR];
    __shared__ float Bs[2][8][BSTR];

    const int tid  = threadIdx.x;
    const int wid  = tid >> 5;
    const int lane = tid & 31;
    const int g = lane >> 2, t = lane & 3;
    const int wm = (wid & 1) * 64;          // warp grid 2(m) x 4(n)
    const int wn = (wid >> 1) * 64;
    const int bm = blockIdx.x * 128;

    const int arow = tid >> 1;              // 0..127
    const int acol = (tid & 1) * 4;         // 0 or 4
    const int brow = tid >> 6;              // 0..3 (and +4)
    const int bcol = (tid & 63) * 4;

    float4 ra, rb0, rb1;
    {
        int r0 = bm + arow;
        ra  = (r0 < M) ? *(const float4*)(A + (size_t)r0 * 256 + acol)
                       : make_float4(0.f, 0.f, 0.f, 0.f);
        rb0 = *(const float4*)(B + (size_t)brow * 256 + bcol);
        rb1 = *(const float4*)(B + (size_t)(brow + 4) * 256 + bcol);
    }
    As[0][acol + 0][arow] = ra.x; As[0][acol + 1][arow] = ra.y;
    As[0][acol + 2][arow] = ra.z; As[0][acol + 3][arow] = ra.w;
    *(float4*)&Bs[0][brow][bcol]     = rb0;
    *(float4*)&Bs[0][brow + 4][bcol] = rb1;
    __syncthreads();

    float acc[4][8][4];
#pragma unroll
    for (int mi = 0; mi < 4; mi++)
#pragma unroll
        for (int ni = 0; ni < 8; ni++)
#pragma unroll
            for (int q = 0; q < 4; q++) acc[mi][ni][q] = 0.f;

    for (int ki = 0; ki < 32; ki++) {
        const int buf = ki & 1;
        if (ki < 31) {
            int k0 = (ki + 1) * 8;
            int r0 = bm + arow;
            ra  = (r0 < M) ? *(const float4*)(A + (size_t)r0 * 256 + k0 + acol)
                           : make_float4(0.f, 0.f, 0.f, 0.f);
            rb0 = *(const float4*)(B + (size_t)(k0 + brow) * 256 + bcol);
            rb1 = *(const float4*)(B + (size_t)(k0 + brow + 4) * 256 + bcol);
        }

        unsigned ahi[4][4], alo[4][4], bhi[8][2], blo[8][2];
#pragma unroll
        for (int mi = 0; mi < 4; mi++) {
            int r0 = wm + mi * 16 + g;
            float v0 = As[buf][t][r0];
            float v1 = As[buf][t][r0 + 8];
            float v2 = As[buf][t + 4][r0];
            float v3 = As[buf][t + 4][r0 + 8];
            split_tf(v0, ahi[mi][0], alo[mi][0]);
            split_tf(v1, ahi[mi][1], alo[mi][1]);
            split_tf(v2, ahi[mi][2], alo[mi][2]);
            split_tf(v3, ahi[mi][3], alo[mi][3]);
        }
#pragma unroll
        for (int ni = 0; ni < 8; ni++) {
            int c0 = wn + ni * 8 + g;
            float w0 = Bs[buf][t][c0];
            float w1 = Bs[buf][t + 4][c0];
            split_tf(w0, bhi[ni][0], blo[ni][0]);
            split_tf(w1, bhi[ni][1], blo[ni][1]);
        }
#pragma unroll
        for (int mi = 0; mi < 4; mi++)
#pragma unroll
            for (int ni = 0; ni < 8; ni++) {
                mma8(acc[mi][ni], alo[mi], bhi[ni]);
                mma8(acc[mi][ni], ahi[mi], blo[ni]);
                mma8(acc[mi][ni], ahi[mi], bhi[ni]);
            }

        if (ki < 31) {
            const int nb = buf ^ 1;
            As[nb][acol + 0][arow] = ra.x; As[nb][acol + 1][arow] = ra.y;
            As[nb][acol + 2][arow] = ra.z; As[nb][acol + 3][arow] = ra.w;
            *(float4*)&Bs[nb][brow][bcol]     = rb0;
            *(float4*)&Bs[nb][brow + 4][bcol] = rb1;
            __syncthreads();
        }
    }

#pragma unroll
    for (int mi = 0; mi < 4; mi++) {
        int row0 = bm + wm + mi * 16 + g;
        int row1 = row0 + 8;
#pragma unroll
        for (int ni = 0; ni < 8; ni++) {
            int col = wn + ni * 8 + 2 * t;
            if (row0 < M)
                *(float2*)(C + (size_t)row0 * ldc + col) =
                    make_float2(acc[mi][ni][0], acc[mi][ni][1]);
            if (row1 < M)
                *(float2*)(C + (size_t)row1 * ldc + col) =
                    make_float2(acc[mi][ni][2], acc[mi][ni][3]);
        }
    }
}

// ============================ attention scores ============================
__global__ void scores_kernel(const float* __restrict__ xw,
                              const float* __restrict__ a_src,
                              const float* __restrict__ a_dst,
                              float* __restrict__ s_src,
                              float* __restrict__ s_dst)
{
    int w = (blockIdx.x * blockDim.x + threadIdx.x) >> 5;
    int lane = threadIdx.x & 31;
    if (w >= Nn) return;
    const float4* xp  = (const float4*)(xw + (size_t)w * DD);
    const float4* asp = (const float4*)a_src;
    const float4* adp = (const float4*)a_dst;
    float ps = 0.f, pd = 0.f;
#pragma unroll
    for (int q = 0; q < 2; q++) {
        int i = lane * 2 + q;
        float4 x4 = xp[i];
        float4 s4 = asp[i], d4 = adp[i];
        ps += x4.x * s4.x + x4.y * s4.y + x4.z * s4.z + x4.w * s4.w;
        pd += x4.x * d4.x + x4.y * d4.y + x4.z * d4.z + x4.w * d4.w;
    }
#pragma unroll
    for (int off = 4; off; off >>= 1) {
        ps += __shfl_down_sync(0xffffffffu, ps, off);
        pd += __shfl_down_sync(0xffffffffu, pd, off);
    }
    if ((lane & 7) == 0) {
        int h = lane >> 3;
        s_src[w * HH + h] = ps;
        s_dst[w * HH + h] = pd;
    }
}

// ============================ softmax passes ============================
__global__ void zero_md_kernel(unsigned* menc, float* den) {
    int i = blockIdx.x * blockDim.x + threadIdx.x;
    if (i < Nn * HH) { menc[i] = 0u; den[i] = 0.f; }
}

__global__ void pass_max_kernel(const float* __restrict__ s_src,
                                const float* __restrict__ s_dst,
                                const int* __restrict__ r, const int* __restrict__ c,
                                float* __restrict__ ex, unsigned* __restrict__ menc)
{
    int e = blockIdx.x * blockDim.x + threadIdx.x;
    if (e >= ETOT) return;
    int ri = r[e], ci = c[e];
    float4 ss = *(const float4*)(s_src + ri * HH);
    float4 sd = *(const float4*)(s_dst + ci * HH);
    float4 l = make_float4(lrelu(ss.x + sd.x), lrelu(ss.y + sd.y),
                           lrelu(ss.z + sd.z), lrelu(ss.w + sd.w));
    *(float4*)(ex + (size_t)e * HH) = l;
    atomicMax(&menc[ci * HH + 0], fenc(l.x));
    atomicMax(&menc[ci * HH + 1], fenc(l.y));
    atomicMax(&menc[ci * HH + 2], fenc(l.z));
    atomicMax(&menc[ci * HH + 3], fenc(l.w));
}

__global__ void pass_exp_kernel(const int* __restrict__ c,
                                const unsigned* __restrict__ menc,
                                float* __restrict__ ex, float* __restrict__ den)
{
    int e = blockIdx.x * blockDim.x + threadIdx.x;
    if (e >= ETOT) return;
    int ci = c[e];
    float4 l = *(const float4*)(ex + (size_t)e * HH);
    uint4 m = *(const uint4*)(menc + ci * HH);
    float4 v = make_float4(expf(l.x - fdec(m.x)), expf(l.y - fdec(m.y)),
                           expf(l.z - fdec(m.z)), expf(l.w - fdec(m.w)));
    *(float4*)(ex + (size_t)e * HH) = v;
    red4(den + ci * HH, v);
}

__global__ void bias_init_kernel(float* __restrict__ out, const float* __restrict__ b) {
    int i = blockIdx.x * blockDim.x + threadIdx.x;
    if (i < Nn * DD) out[i] = b[i & (DD - 1)];
}

// warp per edge: out[c] += alpha_h * xw[r]; also attn accumulation
__global__ void aggregate_kernel(const int* __restrict__ r, const int* __restrict__ c,
                                 const float* __restrict__ ex, const float* __restrict__ den,
                                 const float* __restrict__ xw, float* __restrict__ out,
                                 float* __restrict__ attn, int accumulate)
{
    int e = (blockIdx.x * blockDim.x + threadIdx.x) >> 5;
    int lane = threadIdx.x & 31;
    if (e >= ETOT) return;
    int ri = r[e], ci = c[e];
    int h = lane >> 3;
    float alpha = ex[(size_t)e * HH + h] / den[ci * HH + h];
    const float4* xp = (const float4*)(xw + (size_t)ri * DD);
    float* op = out + (size_t)ci * DD;
#pragma unroll
    for (int q = 0; q < 2; q++) {
        int i = lane * 2 + q;
        float4 v = xp[i];
        v.x *= alpha; v.y *= alpha; v.z *= alpha; v.w *= alpha;
        red4(op + i * 4, v);
    }
    if (lane == 0) {
        float4 e4 = *(const float4*)(ex + (size_t)e * HH);
        float4 d4 = *(const float4*)(den + ci * HH);
        float s = 0.125f * (e4.x / d4.x + e4.y / d4.y + e4.z / d4.z + e4.w / d4.w);
        if (accumulate) attn[e] += s; else attn[e] = s;
    }
}

__global__ void elu_kernel(const float* __restrict__ in, float* __restrict__ out, int n) {
    int i = blockIdx.x * blockDim.x + threadIdx.x;
    if (i < n) {
        float v = in[i];
        out[i] = v > 0.f ? v : (expf(v) - 1.f);
    }
}

// ============================ prediction heads ============================
__global__ void node_pred_kernel(const float* __restrict__ h, const float* __restrict__ Wn,
                                 const float* __restrict__ bn, float* __restrict__ out)
{
    int n = (blockIdx.x * blockDim.x + threadIdx.x) >> 5;
    int lane = threadIdx.x & 31;
    if (n >= Nn) return;
    const float4* hp = (const float4*)(h + (size_t)n * DD);
    const float4* wp = (const float4*)Wn;
    float s = 0.f;
#pragma unroll
    for (int q = 0; q < 2; q++) {
        int i = lane * 2 + q;
        float4 a = hp[i], b = wp[i];
        s += a.x * b.x + a.y * b.y + a.z * b.z + a.w * b.w;
    }
#pragma unroll
    for (int off = 16; off; off >>= 1) s += __shfl_down_sync(0xffffffffu, s, off);
    if (lane == 0) out[n] = s + bn[0];
}

// warp per (original) edge: ep[e,o] = dot(Y[r, o, :], h[c, :]) + bb[o]
__global__ void edge_pred_kernel(const int* __restrict__ r, const int* __restrict__ c,
                                 const float* __restrict__ h, const float* __restrict__ Y,
                                 const float* __restrict__ bb, float* __restrict__ out)
{
    int e = (blockIdx.x * blockDim.x + threadIdx.x) >> 5;
    int lane = threadIdx.x & 31;
    if (e >= Ee) return;
    int ri = r[e], ci = c[e];
    const float4* hp = (const float4*)(h + (size_t)ci * DD);
    float4 h0 = hp[lane * 2], h1 = hp[lane * 2 + 1];
    float s[3];
#pragma unroll
    for (int o = 0; o < 3; o++) {
        const float4* yp = (const float4*)(Y + (size_t)ri * 768 + o * DD);
        float4 y0 = yp[lane * 2], y1 = yp[lane * 2 + 1];
        s[o] = h0.x * y0.x + h0.y * y0.y + h0.z * y0.z + h0.w * y0.w
             + h1.x * y1.x + h1.y * y1.y + h1.z * y1.z + h1.w * y1.w;
    }
#pragma unroll
    for (int off = 16; off; off >>= 1) {
#pragma unroll
        for (int o = 0; o < 3; o++) s[o] += __shfl_down_sync(0xffffffffu, s[o], off);
    }
    if (lane == 0) {
        out[(size_t)e * 3 + 0] = s[0] + bb[0];
        out[(size_t)e * 3 + 1] = s[1] + bb[1];
        out[(size_t)e * 3 + 2] = s[2] + bb[2];
    }
}

// ============================ host launch ============================
extern "C" void kernel_launch(void* const* d_in, const int* in_sizes, int n_in,
                              void* d_out, int out_size)
{
    const float*     x   = (const float*)d_in[0];
    const void*      ei  = d_in[1];
    const float*     W1  = (const float*)d_in[2];
    const float*     a1s = (const float*)d_in[3];
    const float*     a1d = (const float*)d_in[4];
    const float*     b1  = (const float*)d_in[5];
    const float*     W2  = (const float*)d_in[6];
    const float*     a2s = (const float*)d_in[7];
    const float*     a2d = (const float*)d_in[8];
    const float*     b2  = (const float*)d_in[9];
    const float*     Wn  = (const float*)d_in[10];
    const float*     bn  = (const float*)d_in[11];
    const float*     Wb  = (const float*)d_in[12];
    const float*     bb  = (const float*)d_in[13];
    float* out = (float*)d_out;

    float *xw, *h1, *agg, *Y, *ss, *sd, *den, *ex;
    unsigned* menc; int *r, *c;
    cudaGetSymbolAddress((void**)&xw,   g_xw);
    cudaGetSymbolAddress((void**)&h1,   g_h1);
    cudaGetSymbolAddress((void**)&agg,  g_agg);
    cudaGetSymbolAddress((void**)&Y,    g_Y);
    cudaGetSymbolAddress((void**)&ss,   g_ss);
    cudaGetSymbolAddress((void**)&sd,   g_sd);
    cudaGetSymbolAddress((void**)&menc, g_menc);
    cudaGetSymbolAddress((void**)&den,  g_den);
    cudaGetSymbolAddress((void**)&ex,   g_ex);
    cudaGetSymbolAddress((void**)&r,    g_r);
    cudaGetSymbolAddress((void**)&c,    g_c);

    float* hfin = out + H_OFF;
    float* attn = out + AT_OFF;

    const int TB = 256;
    int gemm_grid = (Nn + 127) / 128;           // 391
    int eb    = (ETOT + TB - 1) / TB;
    int ewb   = (ETOT + 7) / 8;
    int nwb   = (Nn + 7) / 8;
    int ndb   = (Nn * DD + TB - 1) / TB;
    int mdb   = (Nn * HH + TB - 1) / TB;

    detect_dtype_kernel<<<1, 32>>>((const long long*)ei);
    conv_idx_kernel<<<eb, TB>>>(ei, r, c);

    // ---------- layer 1 ----------
    gemm_tf32<<<gemm_grid, TB>>>(x, W1, xw, Nn, DD);
    scores_kernel<<<nwb, TB>>>(xw, a1s, a1d, ss, sd);
    zero_md_kernel<<<mdb, TB>>>(menc, den);
    pass_max_kernel<<<eb, TB>>>(ss, sd, r, c, ex, menc);
    pass_exp_kernel<<<eb, TB>>>(c, menc, ex, den);
    bias_init_kernel<<<ndb, TB>>>(agg, b1);
    aggregate_kernel<<<ewb, TB>>>(r, c, ex, den, xw, agg, attn, 0);
    elu_kernel<<<ndb, TB>>>(agg, h1, Nn * DD);

    // ---------- layer 2 ----------
    gemm_tf32<<<gemm_grid, TB>>>(h1, W2, xw, Nn, DD);
    scores_kernel<<<nwb, TB>>>(xw, a2s, a2d, ss, sd);
    zero_md_kernel<<<mdb, TB>>>(menc, den);
    pass_max_kernel<<<eb, TB>>>(ss, sd, r, c, ex, menc);
    pass_exp_kernel<<<eb, TB>>>(c, menc, ex, den);
    bias_init_kernel<<<ndb, TB>>>(hfin, b2);
    aggregate_kernel<<<ewb, TB>>>(r, c, ex, den, xw, hfin, attn, 1);
    elu_kernel<<<ndb, TB>>>(hfin, hfin, Nn * DD);

    // ---------- heads ----------
    node_pred_kernel<<<nwb, TB>>>(hfin, Wn, bn, out + NP_OFF);
    for (int o = 0; o < 3; o++)
        gemm_tf32<<<gemm_grid, TB>>>(hfin, Wb + (size_t)o * DD * DD, Y + o * DD,
                                     Nn, 768);
    edge_pred_kernel<<<(Ee + 7) / 8, TB>>>(r, c, hfin, Y, bb, out + EP_OFF);
}

// round 5
// speedup vs baseline: 1.5792x; 1.3511x over previous
#include <cuda_runtime.h>
#include <cuda_bf16.h>
#include <math.h>

#define Nn   50000
#define Ee   800000
#define ETOT (Ee + Nn)     // 850000
#define DD   256
#define HH   4
#define NEG  0.2f

// ---- output layout (tuple flatten: node_preds, edge_preds, h, attn_weights) ----
#define NP_OFF  0
#define EP_OFF  (Nn)                    // 50000
#define H_OFF   (Nn + 3*Ee)             // 2450000
#define AT_OFF  (H_OFF + Nn*DD)         // 15250000

// ---- scratch (device globals; no allocation allowed) ----
__device__ float    g_xw [Nn * DD];
__device__ float    g_h1 [Nn * DD];
__device__ float    g_Y  [(size_t)Nn * 768];
__device__ float    g_ss [Nn * HH];
__device__ float    g_sd [Nn * HH];
__device__ float    g_ex [ETOT * HH];      // per-edge exp values (CSC order)
__device__ int      g_r[ETOT];
__device__ int      g_c[ETOT];
__device__ int      g_is64;
// CSC (sorted by target c) over all ETOT edges
__device__ int      g_cntc[Nn];
__device__ int      g_offc[Nn + 1];
__device__ int      g_curc[Nn];
__device__ int      g_csc_r[ETOT];
__device__ int      g_csc_e[ETOT];
// CSR (sorted by source r) over original Ee edges
__device__ int      g_cntr[Nn];
__device__ int      g_offr[Nn + 1];
__device__ int      g_curr[Nn];
__device__ int      g_csr_e[Ee];

// ============================ helpers ============================
__device__ __forceinline__ float lrelu(float x) { return x > 0.f ? x : NEG * x; }

__device__ __forceinline__ void split_tf(float v, unsigned& hi, unsigned& lo) {
    asm("cvt.rna.tf32.f32 %0, %1;" : "=r"(hi) : "f"(v));
    lo = __float_as_uint(v - __uint_as_float(hi));
}

__device__ __forceinline__ void mma8(float* c, const unsigned* a, const unsigned* b) {
    asm volatile(
        "mma.sync.aligned.m16n8k8.row.col.f32.tf32.tf32.f32 "
        "{%0,%1,%2,%3}, {%4,%5,%6,%7}, {%8,%9}, {%0,%1,%2,%3};"
        : "+f"(c[0]), "+f"(c[1]), "+f"(c[2]), "+f"(c[3])
        : "r"(a[0]), "r"(a[1]), "r"(a[2]), "r"(a[3]), "r"(b[0]), "r"(b[1]));
}

// ============================ index conversion ============================
__global__ void detect_dtype_kernel(const void* pv) {
    if (blockIdx.x == 0 && threadIdx.x == 0) {
        const long long* p64 = (const long long*)pv;
        const int*       p32 = (const int*)pv;
        int ok64 = 1, ok32 = 1;
        for (int i = 0; i < 256; i++) {
            long long v = p64[i];
            if (v < 0 || v >= Nn) ok64 = 0;
            int w = p32[i];
            if (w < 0 || w >= Nn) ok32 = 0;
        }
        // prefer int64 interpretation when valid (reference dtype is int64)
        g_is64 = ok64 ? 1 : (ok32 ? 0 : 1);
    }
}

__global__ void conv_idx_kernel(const void* pv, int* r, int* c) {
    int e = blockIdx.x * blockDim.x + threadIdx.x;
    if (e >= ETOT) return;
    if (e >= Ee) { r[e] = e - Ee; c[e] = e - Ee; return; }
    int ri, ci;
    if (g_is64) {
        const long long* p = (const long long*)pv;
        ri = (int)p[e]; ci = (int)p[Ee + e];
    } else {
        const int* p = (const int*)pv;
        ri = p[e]; ci = p[Ee + e];
    }
    // clamp: guarantee no downstream OOB regardless of input
    ri = min(max(ri, 0), Nn - 1);
    ci = min(max(ci, 0), Nn - 1);
    r[e] = ri; c[e] = ci;
}

// ============================ counting sort ============================
__global__ void zero_cnt_kernel(int* a, int* b) {
    int i = blockIdx.x * blockDim.x + threadIdx.x;
    if (i < Nn) { a[i] = 0; b[i] = 0; }
}

__global__ void hist_kernel(const int* __restrict__ key, int* cnt, int n) {
    int e = blockIdx.x * blockDim.x + threadIdx.x;
    if (e < n) atomicAdd(&cnt[key[e]], 1);
}

// one-block exclusive scan of 50000 counts -> off[0..50000]
__global__ void scan_kernel(const int* __restrict__ cnt, int* __restrict__ off) {
    __shared__ int part[1024];
    const int tid = threadIdx.x;
    const int CH = (Nn + 1023) / 1024;     // 49
    int base = tid * CH;
    int s = 0;
    for (int i = 0; i < CH; i++) {
        int idx = base + i;
        if (idx < Nn) s += cnt[idx];
    }
    part[tid] = s;
    __syncthreads();
    for (int d = 1; d < 1024; d <<= 1) {
        int v = 0;
        if (tid >= d) v = part[tid - d];
        __syncthreads();
        if (tid >= d) part[tid] += v;
        __syncthreads();
    }
    int run = tid ? part[tid - 1] : 0;
    for (int i = 0; i < CH; i++) {
        int idx = base + i;
        if (idx < Nn) { off[idx] = run; run += cnt[idx]; }
    }
    if (tid == 1023) off[Nn] = part[1023];
}

__global__ void copy_cur_kernel(const int* offc, int* curc, const int* offr, int* curr) {
    int i = blockIdx.x * blockDim.x + threadIdx.x;
    if (i < Nn) { curc[i] = offc[i]; curr[i] = offr[i]; }
}

__global__ void scatter_c_kernel(const int* __restrict__ r, const int* __restrict__ c,
                                 int* cur, int* csc_r, int* csc_e) {
    int e = blockIdx.x * blockDim.x + threadIdx.x;
    if (e >= ETOT) return;
    int j = atomicAdd(&cur[c[e]], 1);
    csc_r[j] = r[e];
    csc_e[j] = e;
}

__global__ void scatter_r_kernel(const int* __restrict__ r, int* cur, int* csr_e) {
    int e = blockIdx.x * blockDim.x + threadIdx.x;
    if (e >= Ee) return;
    int j = atomicAdd(&cur[r[e]], 1);
    csr_e[j] = e;
}

// ============================ 3xTF32 tensor-core GEMM ============================
#define ASTR 136
#define BSTR 264

__global__ __launch_bounds__(256, 1) void gemm_tf32(
    const float* __restrict__ A, const float* __restrict__ B,
    float* __restrict__ C, int M, int ldc)
{
    __shared__ float As[2][8][ASTR];
    __shared__ float Bs[2][8][BSTR];

    const int tid  = threadIdx.x;
    const int wid  = tid >> 5;
    const int lane = tid & 31;
    const int g = lane >> 2, t = lane & 3;
    const int wm = (wid & 1) * 64;
    const int wn = (wid >> 1) * 64;
    const int bm = blockIdx.x * 128;

    const int arow = tid >> 1;
    const int acol = (tid & 1) * 4;
    const int brow = tid >> 6;
    const int bcol = (tid & 63) * 4;

    float4 ra, rb0, rb1;
    {
        int r0 = bm + arow;
        ra  = (r0 < M) ? *(const float4*)(A + (size_t)r0 * 256 + acol)
                       : make_float4(0.f, 0.f, 0.f, 0.f);
        rb0 = *(const float4*)(B + (size_t)brow * 256 + bcol);
        rb1 = *(const float4*)(B + (size_t)(brow + 4) * 256 + bcol);
    }
    As[0][acol + 0][arow] = ra.x; As[0][acol + 1][arow] = ra.y;
    As[0][acol + 2][arow] = ra.z; As[0][acol + 3][arow] = ra.w;
    *(float4*)&Bs[0][brow][bcol]     = rb0;
    *(float4*)&Bs[0][brow + 4][bcol] = rb1;
    __syncthreads();

    float acc[4][8][4];
#pragma unroll
    for (int mi = 0; mi < 4; mi++)
#pragma unroll
        for (int ni = 0; ni < 8; ni++)
#pragma unroll
            for (int q = 0; q < 4; q++) acc[mi][ni][q] = 0.f;

    for (int ki = 0; ki < 32; ki++) {
        const int buf = ki & 1;
        if (ki < 31) {
            int k0 = (ki + 1) * 8;
            int r0 = bm + arow;
            ra  = (r0 < M) ? *(const float4*)(A + (size_t)r0 * 256 + k0 + acol)
                           : make_float4(0.f, 0.f, 0.f, 0.f);
            rb0 = *(const float4*)(B + (size_t)(k0 + brow) * 256 + bcol);
            rb1 = *(const float4*)(B + (size_t)(k0 + brow + 4) * 256 + bcol);
        }

        unsigned ahi[4][4], alo[4][4], bhi[8][2], blo[8][2];
#pragma unroll
        for (int mi = 0; mi < 4; mi++) {
            int r0 = wm + mi * 16 + g;
            float v0 = As[buf][t][r0];
            float v1 = As[buf][t][r0 + 8];
            float v2 = As[buf][t + 4][r0];
            float v3 = As[buf][t + 4][r0 + 8];
            split_tf(v0, ahi[mi][0], alo[mi][0]);
            split_tf(v1, ahi[mi][1], alo[mi][1]);
            split_tf(v2, ahi[mi][2], alo[mi][2]);
            split_tf(v3, ahi[mi][3], alo[mi][3]);
        }
#pragma unroll
        for (int ni = 0; ni < 8; ni++) {
            int c0 = wn + ni * 8 + g;
            float w0 = Bs[buf][t][c0];
            float w1 = Bs[buf][t + 4][c0];
            split_tf(w0, bhi[ni][0], blo[ni][0]);
            split_tf(w1, bhi[ni][1], blo[ni][1]);
        }
#pragma unroll
        for (int mi = 0; mi < 4; mi++)
#pragma unroll
            for (int ni = 0; ni < 8; ni++) {
                mma8(acc[mi][ni], alo[mi], bhi[ni]);
                mma8(acc[mi][ni], ahi[mi], blo[ni]);
                mma8(acc[mi][ni], ahi[mi], bhi[ni]);
            }

        if (ki < 31) {
            const int nb = buf ^ 1;
            As[nb][acol + 0][arow] = ra.x; As[nb][acol + 1][arow] = ra.y;
            As[nb][acol + 2][arow] = ra.z; As[nb][acol + 3][arow] = ra.w;
            *(float4*)&Bs[nb][brow][bcol]     = rb0;
            *(float4*)&Bs[nb][brow + 4][bcol] = rb1;
            __syncthreads();
        }
    }

#pragma unroll
    for (int mi = 0; mi < 4; mi++) {
        int row0 = bm + wm + mi * 16 + g;
        int row1 = row0 + 8;
#pragma unroll
        for (int ni = 0; ni < 8; ni++) {
            int col = wn + ni * 8 + 2 * t;
            if (row0 < M)
                *(float2*)(C + (size_t)row0 * ldc + col) =
                    make_float2(acc[mi][ni][0], acc[mi][ni][1]);
            if (row1 < M)
                *(float2*)(C + (size_t)row1 * ldc + col) =
                    make_float2(acc[mi][ni][2], acc[mi][ni][3]);
        }
    }
}

// ============================ attention scores ============================
__global__ void scores_kernel(const float* __restrict__ xw,
                              const float* __restrict__ a_src,
                              const float* __restrict__ a_dst,
                              float* __restrict__ s_src,
                              float* __restrict__ s_dst)
{
    int w = (blockIdx.x * blockDim.x + threadIdx.x) >> 5;
    int lane = threadIdx.x & 31;
    if (w >= Nn) return;
    const float4* xp  = (const float4*)(xw + (size_t)w * DD);
    const float4* asp = (const float4*)a_src;
    const float4* adp = (const float4*)a_dst;
    float ps = 0.f, pd = 0.f;
#pragma unroll
    for (int q = 0; q < 2; q++) {
        int i = lane * 2 + q;
        float4 x4 = xp[i];
        float4 s4 = asp[i], d4 = adp[i];
        ps += x4.x * s4.x + x4.y * s4.y + x4.z * s4.z + x4.w * s4.w;
        pd += x4.x * d4.x + x4.y * d4.y + x4.z * d4.z + x4.w * d4.w;
    }
#pragma unroll
    for (int off = 4; off; off >>= 1) {
        ps += __shfl_down_sync(0xffffffffu, ps, off);
        pd += __shfl_down_sync(0xffffffffu, pd, off);
    }
    if ((lane & 7) == 0) {
        int h = lane >> 3;
        s_src[w * HH + h] = ps;
        s_dst[w * HH + h] = pd;
    }
}

// ============================ fused GAT layer (warp per node) ============================
// softmax over incoming edges + weighted aggregation + bias + ELU, no atomics.
__global__ __launch_bounds__(256) void gat_fused_kernel(
    const int* __restrict__ off, const int* __restrict__ csc_r,
    const int* __restrict__ csc_e,
    const float* __restrict__ s_src, const float* __restrict__ s_dst,
    const float* __restrict__ xw, const float* __restrict__ bias,
    float* __restrict__ ex, float* __restrict__ outh,
    float* __restrict__ attn, int accumulate)
{
    const int n = (blockIdx.x * blockDim.x + threadIdx.x) >> 5;
    const int lane = threadIdx.x & 31;
    if (n >= Nn) return;

    const int beg = off[n], end = off[n + 1];
    const float4 sd4 = *(const float4*)(s_dst + (size_t)n * HH);

    // ---- pass 1: max over incoming logits (per head) ----
    float4 mx = make_float4(-1e30f, -1e30f, -1e30f, -1e30f);
    for (int j = beg + lane; j < end; j += 32) {
        int ri = csc_r[j];
        float4 ss = *(const float4*)(s_src + (size_t)ri * HH);
        mx.x = fmaxf(mx.x, lrelu(ss.x + sd4.x));
        mx.y = fmaxf(mx.y, lrelu(ss.y + sd4.y));
        mx.z = fmaxf(mx.z, lrelu(ss.z + sd4.z));
        mx.w = fmaxf(mx.w, lrelu(ss.w + sd4.w));
    }
#pragma unroll
    for (int o = 16; o; o >>= 1) {
        mx.x = fmaxf(mx.x, __shfl_xor_sync(0xffffffffu, mx.x, o));
        mx.y = fmaxf(mx.y, __shfl_xor_sync(0xffffffffu, mx.y, o));
        mx.z = fmaxf(mx.z, __shfl_xor_sync(0xffffffffu, mx.z, o));
        mx.w = fmaxf(mx.w, __shfl_xor_sync(0xffffffffu, mx.w, o));
    }

    // ---- pass 2: exp, write ex, accumulate denominator ----
    float4 den = make_float4(0.f, 0.f, 0.f, 0.f);
    for (int j = beg + lane; j < end; j += 32) {
        int ri = csc_r[j];
        float4 ss = *(const float4*)(s_src + (size_t)ri * HH);
        float4 v;
        v.x = expf(lrelu(ss.x + sd4.x) - mx.x);
        v.y = expf(lrelu(ss.y + sd4.y) - mx.y);
        v.z = expf(lrelu(ss.z + sd4.z) - mx.z);
        v.w = expf(lrelu(ss.w + sd4.w) - mx.w);
        *(float4*)(ex + (size_t)j * HH) = v;
        den.x += v.x; den.y += v.y; den.z += v.z; den.w += v.w;
    }
#pragma unroll
    for (int o = 16; o; o >>= 1) {
        den.x += __shfl_xor_sync(0xffffffffu, den.x, o);
        den.y += __shfl_xor_sync(0xffffffffu, den.y, o);
        den.z += __shfl_xor_sync(0xffffffffu, den.z, o);
        den.w += __shfl_xor_sync(0xffffffffu, den.w, o);
    }
    const float4 inv = make_float4(1.f / den.x, 1.f / den.y, 1.f / den.z, 1.f / den.w);
    __syncwarp();

    // ---- pass 2b: attention weight output (per-lane parallel, ex is L1-hot) ----
    for (int j = beg + lane; j < end; j += 32) {
        float4 v = *(const float4*)(ex + (size_t)j * HH);
        float s = 0.125f * (v.x * inv.x + v.y * inv.y + v.z * inv.z + v.w * inv.w);
        int oe = csc_e[j];
        if (accumulate) attn[oe] += s; else attn[oe] = s;
    }

    // ---- pass 3: aggregate ----
    const int h = lane >> 3;
    const float invh = (h == 0) ? inv.x : (h == 1) ? inv.y : (h == 2) ? inv.z : inv.w;
    const int col = lane * 8;

    const float4* b4 = (const float4*)(bias);
    float4 a0 = b4[lane * 2], a1 = b4[lane * 2 + 1];

    for (int j = beg; j < end; j++) {
        int ri = csc_r[j];                      // broadcast
        float exh = ex[(size_t)j * HH + h];     // 16B line broadcast
        float alpha = exh * invh;
        const float4* xp = (const float4*)(xw + (size_t)ri * DD + col);
        float4 v0 = xp[0], v1 = xp[1];
        a0.x += alpha * v0.x; a0.y += alpha * v0.y;
        a0.z += alpha * v0.z; a0.w += alpha * v0.w;
        a1.x += alpha * v1.x; a1.y += alpha * v1.y;
        a1.z += alpha * v1.z; a1.w += alpha * v1.w;
    }

    // ---- ELU + store ----
    a0.x = a0.x > 0.f ? a0.x : expf(a0.x) - 1.f;
    a0.y = a0.y > 0.f ? a0.y : expf(a0.y) - 1.f;
    a0.z = a0.z > 0.f ? a0.z : expf(a0.z) - 1.f;
    a0.w = a0.w > 0.f ? a0.w : expf(a0.w) - 1.f;
    a1.x = a1.x > 0.f ? a1.x : expf(a1.x) - 1.f;
    a1.y = a1.y > 0.f ? a1.y : expf(a1.y) - 1.f;
    a1.z = a1.z > 0.f ? a1.z : expf(a1.z) - 1.f;
    a1.w = a1.w > 0.f ? a1.w : expf(a1.w) - 1.f;
    float4* op = (float4*)(outh + (size_t)n * DD + col);
    op[0] = a0; op[1] = a1;
}

// ============================ prediction heads ============================
__global__ void node_pred_kernel(const float* __restrict__ h, const float* __restrict__ Wn,
                                 const float* __restrict__ bn, float* __restrict__ out)
{
    int n = (blockIdx.x * blockDim.x + threadIdx.x) >> 5;
    int lane = threadIdx.x & 31;
    if (n >= Nn) return;
    const float4* hp = (const float4*)(h + (size_t)n * DD);
    const float4* wp = (const float4*)Wn;
    float s = 0.f;
#pragma unroll
    for (int q = 0; q < 2; q++) {
        int i = lane * 2 + q;
        float4 a = hp[i], b = wp[i];
        s += a.x * b.x + a.y * b.y + a.z * b.z + a.w * b.w;
    }
#pragma unroll
    for (int off = 16; off; off >>= 1) s += __shfl_down_sync(0xffffffffu, s, off);
    if (lane == 0) out[n] = s + bn[0];
}

// warp per sorted edge: ep[oe,o] = dot(Y[r,o,:], h[c,:]) + bb[o]
__global__ void edge_pred_kernel(const int* __restrict__ csr_e,
                                 const int* __restrict__ r, const int* __restrict__ c,
                                 const float* __restrict__ h, const float* __restrict__ Y,
                                 const float* __restrict__ bb, float* __restrict__ out)
{
    int j = (blockIdx.x * blockDim.x + threadIdx.x) >> 5;
    int lane = threadIdx.x & 31;
    if (j >= Ee) return;
    int oe = csr_e[j];
    int ri = r[oe], ci = c[oe];
    const float4* hp = (const float4*)(h + (size_t)ci * DD);
    float4 h0 = hp[lane * 2], h1 = hp[lane * 2 + 1];
    float s[3];
#pragma unroll
    for (int o = 0; o < 3; o++) {
        const float4* yp = (const float4*)(Y + (size_t)ri * 768 + o * DD);
        float4 y0 = yp[lane * 2], y1 = yp[lane * 2 + 1];
        s[o] = h0.x * y0.x + h0.y * y0.y + h0.z * y0.z + h0.w * y0.w
             + h1.x * y1.x + h1.y * y1.y + h1.z * y1.z + h1.w * y1.w;
    }
#pragma unroll
    for (int off = 16; off; off >>= 1) {
#pragma unroll
        for (int o = 0; o < 3; o++) s[o] += __shfl_down_sync(0xffffffffu, s[o], off);
    }
    if (lane == 0) {
        out[(size_t)oe * 3 + 0] = s[0] + bb[0];
        out[(size_t)oe * 3 + 1] = s[1] + bb[1];
        out[(size_t)oe * 3 + 2] = s[2] + bb[2];
    }
}

// ============================ host launch ============================
extern "C" void kernel_launch(void* const* d_in, const int* in_sizes, int n_in,
                              void* d_out, int out_size)
{
    const float*     x   = (const float*)d_in[0];
    const void*      ei  = d_in[1];
    const float*     W1  = (const float*)d_in[2];
    const float*     a1s = (const float*)d_in[3];
    const float*     a1d = (const float*)d_in[4];
    const float*     b1  = (const float*)d_in[5];
    const float*     W2  = (const float*)d_in[6];
    const float*     a2s = (const float*)d_in[7];
    const float*     a2d = (const float*)d_in[8];
    const float*     b2  = (const float*)d_in[9];
    const float*     Wn  = (const float*)d_in[10];
    const float*     bn  = (const float*)d_in[11];
    const float*     Wb  = (const float*)d_in[12];
    const float*     bb  = (const float*)d_in[13];
    float* out = (float*)d_out;

    float *xw, *h1, *Y, *ss, *sd, *ex;
    int *r, *c, *cntc, *offc, *curc, *csc_r, *csc_e;
    int *cntr, *offr, *curr, *csr_e;
    cudaGetSymbolAddress((void**)&xw,    g_xw);
    cudaGetSymbolAddress((void**)&h1,    g_h1);
    cudaGetSymbolAddress((void**)&Y,     g_Y);
    cudaGetSymbolAddress((void**)&ss,    g_ss);
    cudaGetSymbolAddress((void**)&sd,    g_sd);
    cudaGetSymbolAddress((void**)&ex,    g_ex);
    cudaGetSymbolAddress((void**)&r,     g_r);
    cudaGetSymbolAddress((void**)&c,     g_c);
    cudaGetSymbolAddress((void**)&cntc,  g_cntc);
    cudaGetSymbolAddress((void**)&offc,  g_offc);
    cudaGetSymbolAddress((void**)&curc,  g_curc);
    cudaGetSymbolAddress((void**)&csc_r, g_csc_r);
    cudaGetSymbolAddress((void**)&csc_e, g_csc_e);
    cudaGetSymbolAddress((void**)&cntr,  g_cntr);
    cudaGetSymbolAddress((void**)&offr,  g_offr);
    cudaGetSymbolAddress((void**)&curr,  g_curr);
    cudaGetSymbolAddress((void**)&csr_e, g_csr_e);

    float* hfin = out + H_OFF;
    float* attn = out + AT_OFF;

    const int TB = 256;
    int gemm_grid = (Nn + 127) / 128;
    int eb  = (ETOT + TB - 1) / TB;
    int e0b = (Ee + TB - 1) / TB;
    int nb  = (Nn + TB - 1) / TB;
    int nwb = (Nn + 7) / 8;

    detect_dtype_kernel<<<1, 32>>>(ei);
    conv_idx_kernel<<<eb, TB>>>(ei, r, c);

    // ---------- build CSC (by target) and CSR (by source) ----------
    zero_cnt_kernel<<<nb, TB>>>(cntc, cntr);
    hist_kernel<<<eb, TB>>>(c, cntc, ETOT);
    hist_kernel<<<e0b, TB>>>(r, cntr, Ee);
    scan_kernel<<<1, 1024>>>(cntc, offc);
    scan_kernel<<<1, 1024>>>(cntr, offr);
    copy_cur_kernel<<<nb, TB>>>(offc, curc, offr, curr);
    scatter_c_kernel<<<eb, TB>>>(r, c, curc, csc_r, csc_e);
    scatter_r_kernel<<<e0b, TB>>>(r, curr, csr_e);

    // ---------- layer 1 ----------
    gemm_tf32<<<gemm_grid, TB>>>(x, W1, xw, Nn, DD);
    scores_kernel<<<nwb, TB>>>(xw, a1s, a1d, ss, sd);
    gat_fused_kernel<<<nwb, TB>>>(offc, csc_r, csc_e, ss, sd, xw, b1, ex, h1, attn, 0);

    // ---------- layer 2 ----------
    gemm_tf32<<<gemm_grid, TB>>>(h1, W2, xw, Nn, DD);
    scores_kernel<<<nwb, TB>>>(xw, a2s, a2d, ss, sd);
    gat_fused_kernel<<<nwb, TB>>>(offc, csc_r, csc_e, ss, sd, xw, b2, ex, hfin, attn, 1);

    // ---------- heads ----------
    node_pred_kernel<<<nwb, TB>>>(hfin, Wn, bn, out + NP_OFF);
    for (int o = 0; o < 3; o++)
        gemm_tf32<<<gemm_grid, TB>>>(hfin, Wb + (size_t)o * DD * DD, Y + o * DD,
                                     Nn, 768);
    edge_pred_kernel<<<(Ee + 7) / 8, TB>>>(csr_e, r, c, hfin, Y, bb, out + EP_OFF);
}

// round 7
// speedup vs baseline: 1.8269x; 1.1568x over previous
#include <cuda_runtime.h>
#include <cuda_bf16.h>
#include <math.h>

#define Nn   50000
#define Ee   800000
#define ETOT (Ee + Nn)     // 850000
#define DD   256
#define HH   4
#define NEG  0.2f

// ---- output layout (tuple flatten: node_preds, edge_preds, h, attn_weights) ----
#define NP_OFF  0
#define EP_OFF  (Nn)                    // 50000
#define H_OFF   (Nn + 3*Ee)             // 2450000
#define AT_OFF  (H_OFF + Nn*DD)         // 15250000

// ---- scratch (device globals; no allocation allowed) ----
__device__ float    g_xw [Nn * DD];
__device__ float    g_h1 [Nn * DD];
__device__ float    g_Y  [(size_t)Nn * 768];
__device__ float    g_ss [Nn * HH];
__device__ float    g_sd [Nn * HH];
__device__ float    g_ex [ETOT * HH];      // per-edge exp values (CSC order)
__device__ int      g_r[ETOT];
__device__ int      g_c[ETOT];
__device__ int      g_is64;
// CSC (sorted by target c) over all ETOT edges
__device__ int      g_cntc[Nn];
__device__ int      g_offc[Nn + 1];
__device__ int      g_curc[Nn];
__device__ int      g_csc_r[ETOT];
__device__ int      g_csc_e[ETOT];
// CSR (sorted by source r) over original Ee edges
__device__ int      g_cntr[Nn];
__device__ int      g_offr[Nn + 1];
__device__ int      g_curr[Nn];
__device__ int      g_csr_e[Ee];

// ============================ helpers ============================
__device__ __forceinline__ float lrelu(float x) { return x > 0.f ? x : NEG * x; }

// pack upper-16 (truncated bf16) of two floats: low half <- a, high half <- b
__device__ __forceinline__ unsigned pack_hi2(float a, float b) {
    return __byte_perm(__float_as_uint(a), __float_as_uint(b), 0x7632);
}
// residual after truncation split
__device__ __forceinline__ float resid(float v) {
    return v - __uint_as_float(__float_as_uint(v) & 0xffff0000u);
}
// pack bf16(lo_a) into low half, bf16(lo_b) into high half
__device__ __forceinline__ unsigned pack_lo2(float a, float b) {
    unsigned d;
    asm("cvt.rn.bf16x2.f32 %0, %1, %2;" : "=r"(d) : "f"(b), "f"(a));
    return d;
}

__device__ __forceinline__ void mma16(float* c, const unsigned* a, const unsigned* b) {
    asm volatile(
        "mma.sync.aligned.m16n8k16.row.col.f32.bf16.bf16.f32 "
        "{%0,%1,%2,%3}, {%4,%5,%6,%7}, {%8,%9}, {%0,%1,%2,%3};"
        : "+f"(c[0]), "+f"(c[1]), "+f"(c[2]), "+f"(c[3])
        : "r"(a[0]), "r"(a[1]), "r"(a[2]), "r"(a[3]), "r"(b[0]), "r"(b[1]));
}

// ============================ index conversion ============================
__global__ void detect_dtype_kernel(const void* pv) {
    if (blockIdx.x == 0 && threadIdx.x == 0) {
        const long long* p64 = (const long long*)pv;
        const int*       p32 = (const int*)pv;
        int ok64 = 1, ok32 = 1;
        for (int i = 0; i < 256; i++) {
            long long v = p64[i];
            if (v < 0 || v >= Nn) ok64 = 0;
            int w = p32[i];
            if (w < 0 || w >= Nn) ok32 = 0;
        }
        g_is64 = ok64 ? 1 : (ok32 ? 0 : 1);
    }
}

__global__ void conv_idx_kernel(const void* pv, int* r, int* c) {
    int e = blockIdx.x * blockDim.x + threadIdx.x;
    if (e >= ETOT) return;
    if (e >= Ee) { r[e] = e - Ee; c[e] = e - Ee; return; }
    int ri, ci;
    if (g_is64) {
        const long long* p = (const long long*)pv;
        ri = (int)p[e]; ci = (int)p[Ee + e];
    } else {
        const int* p = (const int*)pv;
        ri = p[e]; ci = p[Ee + e];
    }
    ri = min(max(ri, 0), Nn - 1);
    ci = min(max(ci, 0), Nn - 1);
    r[e] = ri; c[e] = ci;
}

// ============================ counting sort ============================
__global__ void zero_cnt_kernel(int* a, int* b) {
    int i = blockIdx.x * blockDim.x + threadIdx.x;
    if (i < Nn) { a[i] = 0; b[i] = 0; }
}

__global__ void hist_kernel(const int* __restrict__ key, int* cnt, int n) {
    int e = blockIdx.x * blockDim.x + threadIdx.x;
    if (e < n) atomicAdd(&cnt[key[e]], 1);
}

__global__ void scan_kernel(const int* __restrict__ cnt, int* __restrict__ off) {
    __shared__ int part[1024];
    const int tid = threadIdx.x;
    const int CH = (Nn + 1023) / 1024;     // 49
    int base = tid * CH;
    int s = 0;
    for (int i = 0; i < CH; i++) {
        int idx = base + i;
        if (idx < Nn) s += cnt[idx];
    }
    part[tid] = s;
    __syncthreads();
    for (int d = 1; d < 1024; d <<= 1) {
        int v = 0;
        if (tid >= d) v = part[tid - d];
        __syncthreads();
        if (tid >= d) part[tid] += v;
        __syncthreads();
    }
    int run = tid ? part[tid - 1] : 0;
    for (int i = 0; i < CH; i++) {
        int idx = base + i;
        if (idx < Nn) { off[idx] = run; run += cnt[idx]; }
    }
    if (tid == 1023) off[Nn] = part[1023];
}

__global__ void copy_cur_kernel(const int* offc, int* curc, const int* offr, int* curr) {
    int i = blockIdx.x * blockDim.x + threadIdx.x;
    if (i < Nn) { curc[i] = offc[i]; curr[i] = offr[i]; }
}

__global__ void scatter_c_kernel(const int* __restrict__ r, const int* __restrict__ c,
                                 int* cur, int* csc_r, int* csc_e) {
    int e = blockIdx.x * blockDim.x + threadIdx.x;
    if (e >= ETOT) return;
    int j = atomicAdd(&cur[c[e]], 1);
    csc_r[j] = r[e];
    csc_e[j] = e;
}

__global__ void scatter_r_kernel(const int* __restrict__ r, int* cur, int* csr_e) {
    int e = blockIdx.x * blockDim.x + threadIdx.x;
    if (e >= Ee) return;
    int j = atomicAdd(&cur[r[e]], 1);
    csr_e[j] = e;
}

// ============================ 3x-bf16 tensor-core GEMM ============================
// C[M, 256] = A[M, 256] @ B[256, 256] using m16n8k16 bf16 mma with 3-term
// error compensation (hi*hi + hi*lo + lo*hi). BK=16, double-buffered dyn smem.
#define ASTR 132   // stride mod 32 = 4 -> frag loads conflict-free
#define BSTR 260
#define ABUF (16 * ASTR)
#define BBUF (16 * BSTR)
#define GEMM_SMEM ((2 * ABUF + 2 * BBUF) * 4)

__global__ __launch_bounds__(256, 1) void gemm_bf16x3(
    const float* __restrict__ A, const float* __restrict__ B,
    float* __restrict__ C, int M, int ldc)
{
    extern __shared__ float sm[];
    float* Asb = sm;                  // [2][16][ASTR]
    float* Bsb = sm + 2 * ABUF;       // [2][16][BSTR]

    const int tid  = threadIdx.x;
    const int wid  = tid >> 5;
    const int lane = tid & 31;
    const int g = lane >> 2, t = lane & 3;
    const int wm = (wid & 1) * 64;
    const int wn = (wid >> 1) * 64;
    const int bm = blockIdx.x * 128;

    const int arow = tid >> 1;              // 0..127
    const int acol = (tid & 1) * 8;         // 0 or 8
    const int brow = tid >> 4;              // 0..15
    const int bcol = (tid & 15) * 16;       // 0..240

    float4 ra0, ra1, rb[4];
    {
        int r0 = bm + arow;
        if (r0 < M) {
            ra0 = *(const float4*)(A + (size_t)r0 * 256 + acol);
            ra1 = *(const float4*)(A + (size_t)r0 * 256 + acol + 4);
        } else { ra0 = make_float4(0,0,0,0); ra1 = ra0; }
#pragma unroll
        for (int q = 0; q < 4; q++)
            rb[q] = *(const float4*)(B + (size_t)brow * 256 + bcol + q * 4);
    }
    {
        float* As = Asb;
        As[(acol+0)*ASTR + arow] = ra0.x; As[(acol+1)*ASTR + arow] = ra0.y;
        As[(acol+2)*ASTR + arow] = ra0.z; As[(acol+3)*ASTR + arow] = ra0.w;
        As[(acol+4)*ASTR + arow] = ra1.x; As[(acol+5)*ASTR + arow] = ra1.y;
        As[(acol+6)*ASTR + arow] = ra1.z; As[(acol+7)*ASTR + arow] = ra1.w;
        float* Bsr = Bsb + brow * BSTR;
#pragma unroll
        for (int q = 0; q < 4; q++)
            *(float4*)(Bsr + bcol + q * 4) = rb[q];
    }
    __syncthreads();

    float acc[4][8][4];
#pragma unroll
    for (int mi = 0; mi < 4; mi++)
#pragma unroll
        for (int ni = 0; ni < 8; ni++)
#pragma unroll
            for (int q = 0; q < 4; q++) acc[mi][ni][q] = 0.f;

    for (int ki = 0; ki < 16; ki++) {
        const int buf = ki & 1;
        if (ki < 15) {
            int k0 = (ki + 1) * 16;
            int r0 = bm + arow;
            if (r0 < M) {
                ra0 = *(const float4*)(A + (size_t)r0 * 256 + k0 + acol);
                ra1 = *(const float4*)(A + (size_t)r0 * 256 + k0 + acol + 4);
            } else { ra0 = make_float4(0,0,0,0); ra1 = ra0; }
#pragma unroll
            for (int q = 0; q < 4; q++)
                rb[q] = *(const float4*)(B + (size_t)(k0 + brow) * 256 + bcol + q * 4);
        }

        const float* As = Asb + buf * ABUF;
        const float* Bs = Bsb + buf * BBUF;

        unsigned ahi[4][4], alo[4][4], bhi[8][2], blo[8][2];
#pragma unroll
        for (int mi = 0; mi < 4; mi++) {
            int r0 = wm + mi * 16 + g;
            float v00 = As[(2*t  )*ASTR + r0], v01 = As[(2*t+1)*ASTR + r0];
            float v10 = As[(2*t  )*ASTR + r0+8], v11 = As[(2*t+1)*ASTR + r0+8];
            float v20 = As[(2*t+8)*ASTR + r0], v21 = As[(2*t+9)*ASTR + r0];
            float v30 = As[(2*t+8)*ASTR + r0+8], v31 = As[(2*t+9)*ASTR + r0+8];
            ahi[mi][0] = pack_hi2(v00, v01); alo[mi][0] = pack_lo2(resid(v00), resid(v01));
            ahi[mi][1] = pack_hi2(v10, v11); alo[mi][1] = pack_lo2(resid(v10), resid(v11));
            ahi[mi][2] = pack_hi2(v20, v21); alo[mi][2] = pack_lo2(resid(v20), resid(v21));
            ahi[mi][3] = pack_hi2(v30, v31); alo[mi][3] = pack_lo2(resid(v30), resid(v31));
        }
#pragma unroll
        for (int ni = 0; ni < 8; ni++) {
            int c0 = wn + ni * 8 + g;
            float w00 = Bs[(2*t  )*BSTR + c0], w01 = Bs[(2*t+1)*BSTR + c0];
            float w10 = Bs[(2*t+8)*BSTR + c0], w11 = Bs[(2*t+9)*BSTR + c0];
            bhi[ni][0] = pack_hi2(w00, w01); blo[ni][0] = pack_lo2(resid(w00), resid(w01));
            bhi[ni][1] = pack_hi2(w10, w11); blo[ni][1] = pack_lo2(resid(w10), resid(w11));
        }
#pragma unroll
        for (int mi = 0; mi < 4; mi++)
#pragma unroll
            for (int ni = 0; ni < 8; ni++) {
                mma16(acc[mi][ni], alo[mi], bhi[ni]);
                mma16(acc[mi][ni], ahi[mi], blo[ni]);
                mma16(acc[mi][ni], ahi[mi], bhi[ni]);
            }

        if (ki < 15) {
            const int nb = buf ^ 1;
            float* Asn = Asb + nb * ABUF;
            Asn[(acol+0)*ASTR + arow] = ra0.x; Asn[(acol+1)*ASTR + arow] = ra0.y;
            Asn[(acol+2)*ASTR + arow] = ra0.z; Asn[(acol+3)*ASTR + arow] = ra0.w;
            Asn[(acol+4)*ASTR + arow] = ra1.x; Asn[(acol+5)*ASTR + arow] = ra1.y;
            Asn[(acol+6)*ASTR + arow] = ra1.z; Asn[(acol+7)*ASTR + arow] = ra1.w;
            float* Bsn = Bsb + nb * BBUF + brow * BSTR;
#pragma unroll
            for (int q = 0; q < 4; q++)
                *(float4*)(Bsn + bcol + q * 4) = rb[q];
            __syncthreads();
        }
    }

#pragma unroll
    for (int mi = 0; mi < 4; mi++) {
        int row0 = bm + wm + mi * 16 + g;
        int row1 = row0 + 8;
#pragma unroll
        for (int ni = 0; ni < 8; ni++) {
            int col = wn + ni * 8 + 2 * t;
            if (row0 < M)
                *(float2*)(C + (size_t)row0 * ldc + col) =
                    make_float2(acc[mi][ni][0], acc[mi][ni][1]);
            if (row1 < M)
                *(float2*)(C + (size_t)row1 * ldc + col) =
                    make_float2(acc[mi][ni][2], acc[mi][ni][3]);
        }
    }
}

// ============================ attention scores ============================
__global__ void scores_kernel(const float* __restrict__ xw,
                              const float* __restrict__ a_src,
                              const float* __restrict__ a_dst,
                              float* __restrict__ s_src,
                              float* __restrict__ s_dst)
{
    int w = (blockIdx.x * blockDim.x + threadIdx.x) >> 5;
    int lane = threadIdx.x & 31;
    if (w >= Nn) return;
    const float4* xp  = (const float4*)(xw + (size_t)w * DD);
    const float4* asp = (const float4*)a_src;
    const float4* adp = (const float4*)a_dst;
    float ps = 0.f, pd = 0.f;
#pragma unroll
    for (int q = 0; q < 2; q++) {
        int i = lane * 2 + q;
        float4 x4 = xp[i];
        float4 s4 = asp[i], d4 = adp[i];
        ps += x4.x * s4.x + x4.y * s4.y + x4.z * s4.z + x4.w * s4.w;
        pd += x4.x * d4.x + x4.y * d4.y + x4.z * d4.z + x4.w * d4.w;
    }
#pragma unroll
    for (int off = 4; off; off >>= 1) {
        ps += __shfl_down_sync(0xffffffffu, ps, off);
        pd += __shfl_down_sync(0xffffffffu, pd, off);
    }
    if ((lane & 7) == 0) {
        int h = lane >> 3;
        s_src[w * HH + h] = ps;
        s_dst[w * HH + h] = pd;
    }
}

// ============================ fused GAT layer (warp per node) ============================
__global__ __launch_bounds__(256) void gat_fused_kernel(
    const int* __restrict__ off, const int* __restrict__ csc_r,
    const int* __restrict__ csc_e,
    const float* __restrict__ s_src, const float* __restrict__ s_dst,
    const float* __restrict__ xw, const float* __restrict__ bias,
    float* __restrict__ ex, float* __restrict__ outh,
    float* __restrict__ attn, int accumulate)
{
    const int n = (blockIdx.x * blockDim.x + threadIdx.x) >> 5;
    const int lane = threadIdx.x & 31;
    if (n >= Nn) return;

    const int beg = off[n], end = off[n + 1];
    const float4 sd4 = *(const float4*)(s_dst + (size_t)n * HH);

    float4 mx = make_float4(-1e30f, -1e30f, -1e30f, -1e30f);
    for (int j = beg + lane; j < end; j += 32) {
        int ri = csc_r[j];
        float4 ss = *(const float4*)(s_src + (size_t)ri * HH);
        mx.x = fmaxf(mx.x, lrelu(ss.x + sd4.x));
        mx.y = fmaxf(mx.y, lrelu(ss.y + sd4.y));
        mx.z = fmaxf(mx.z, lrelu(ss.z + sd4.z));
        mx.w = fmaxf(mx.w, lrelu(ss.w + sd4.w));
    }
#pragma unroll
    for (int o = 16; o; o >>= 1) {
        mx.x = fmaxf(mx.x, __shfl_xor_sync(0xffffffffu, mx.x, o));
        mx.y = fmaxf(mx.y, __shfl_xor_sync(0xffffffffu, mx.y, o));
        mx.z = fmaxf(mx.z, __shfl_xor_sync(0xffffffffu, mx.z, o));
        mx.w = fmaxf(mx.w, __shfl_xor_sync(0xffffffffu, mx.w, o));
    }

    float4 den = make_float4(0.f, 0.f, 0.f, 0.f);
    for (int j = beg + lane; j < end; j += 32) {
        int ri = csc_r[j];
        float4 ss = *(const float4*)(s_src + (size_t)ri * HH);
        float4 v;
        v.x = expf(lrelu(ss.x + sd4.x) - mx.x);
        v.y = expf(lrelu(ss.y + sd4.y) - mx.y);
        v.z = expf(lrelu(ss.z + sd4.z) - mx.z);
        v.w = expf(lrelu(ss.w + sd4.w) - mx.w);
        *(float4*)(ex + (size_t)j * HH) = v;
        den.x += v.x; den.y += v.y; den.z += v.z; den.w += v.w;
    }
#pragma unroll
    for (int o = 16; o; o >>= 1) {
        den.x += __shfl_xor_sync(0xffffffffu, den.x, o);
        den.y += __shfl_xor_sync(0xffffffffu, den.y, o);
        den.z += __shfl_xor_sync(0xffffffffu, den.z, o);
        den.w += __shfl_xor_sync(0xffffffffu, den.w, o);
    }
    const float4 inv = make_float4(1.f / den.x, 1.f / den.y, 1.f / den.z, 1.f / den.w);
    __syncwarp();

    for (int j = beg + lane; j < end; j += 32) {
        float4 v = *(const float4*)(ex + (size_t)j * HH);
        float s = 0.125f * (v.x * inv.x + v.y * inv.y + v.z * inv.z + v.w * inv.w);
        int oe = csc_e[j];
        if (accumulate) attn[oe] += s; else attn[oe] = s;
    }

    const int h = lane >> 3;
    const float invh = (h == 0) ? inv.x : (h == 1) ? inv.y : (h == 2) ? inv.z : inv.w;
    const int col = lane * 8;

    const float4* b4 = (const float4*)(bias);
    float4 a0 = b4[lane * 2], a1 = b4[lane * 2 + 1];

    for (int j = beg; j < end; j++) {
        int ri = csc_r[j];
        float exh = ex[(size_t)j * HH + h];
        float alpha = exh * invh;
        const float4* xp = (const float4*)(xw + (size_t)ri * DD + col);
        float4 v0 = xp[0], v1 = xp[1];
        a0.x += alpha * v0.x; a0.y += alpha * v0.y;
        a0.z += alpha * v0.z; a0.w += alpha * v0.w;
        a1.x += alpha * v1.x; a1.y += alpha * v1.y;
        a1.z += alpha * v1.z; a1.w += alpha * v1.w;
    }

    a0.x = a0.x > 0.f ? a0.x : expf(a0.x) - 1.f;
    a0.y = a0.y > 0.f ? a0.y : expf(a0.y) - 1.f;
    a0.z = a0.z > 0.f ? a0.z : expf(a0.z) - 1.f;
    a0.w = a0.w > 0.f ? a0.w : expf(a0.w) - 1.f;
    a1.x = a1.x > 0.f ? a1.x : expf(a1.x) - 1.f;
    a1.y = a1.y > 0.f ? a1.y : expf(a1.y) - 1.f;
    a1.z = a1.z > 0.f ? a1.z : expf(a1.z) - 1.f;
    a1.w = a1.w > 0.f ? a1.w : expf(a1.w) - 1.f;
    float4* op = (float4*)(outh + (size_t)n * DD + col);
    op[0] = a0; op[1] = a1;
}

// ============================ prediction heads ============================
__global__ void node_pred_kernel(const float* __restrict__ h, const float* __restrict__ Wn,
                                 const float* __restrict__ bn, float* __restrict__ out)
{
    int n = (blockIdx.x * blockDim.x + threadIdx.x) >> 5;
    int lane = threadIdx.x & 31;
    if (n >= Nn) return;
    const float4* hp = (const float4*)(h + (size_t)n * DD);
    const float4* wp = (const float4*)Wn;
    float s = 0.f;
#pragma unroll
    for (int q = 0; q < 2; q++) {
        int i = lane * 2 + q;
        float4 a = hp[i], b = wp[i];
        s += a.x * b.x + a.y * b.y + a.z * b.z + a.w * b.w;
    }
#pragma unroll
    for (int off = 16; off; off >>= 1) s += __shfl_down_sync(0xffffffffu, s, off);
    if (lane == 0) out[n] = s + bn[0];
}

__global__ void edge_pred_kernel(const int* __restrict__ csr_e,
                                 const int* __restrict__ r, const int* __restrict__ c,
                                 const float* __restrict__ h, const float* __restrict__ Y,
                                 const float* __restrict__ bb, float* __restrict__ out)
{
    int j = (blockIdx.x * blockDim.x + threadIdx.x) >> 5;
    int lane = threadIdx.x & 31;
    if (j >= Ee) return;
    int oe = csr_e[j];
    int ri = r[oe], ci = c[oe];
    const float4* hp = (const float4*)(h + (size_t)ci * DD);
    float4 h0 = hp[lane * 2], h1 = hp[lane * 2 + 1];
    float s[3];
#pragma unroll
    for (int o = 0; o < 3; o++) {
        const float4* yp = (const float4*)(Y + (size_t)ri * 768 + o * DD);
        float4 y0 = yp[lane * 2], y1 = yp[lane * 2 + 1];
        s[o] = h0.x * y0.x + h0.y * y0.y + h0.z * y0.z + h0.w * y0.w
             + h1.x * y1.x + h1.y * y1.y + h1.z * y1.z + h1.w * y1.w;
    }
#pragma unroll
    for (int off = 16; off; off >>= 1) {
#pragma unroll
        for (int o = 0; o < 3; o++) s[o] += __shfl_down_sync(0xffffffffu, s[o], off);
    }
    if (lane == 0) {
        out[(size_t)oe * 3 + 0] = s[0] + bb[0];
        out[(size_t)oe * 3 + 1] = s[1] + bb[1];
        out[(size_t)oe * 3 + 2] = s[2] + bb[2];
    }
}

// ============================ host launch ============================
extern "C" void kernel_launch(void* const* d_in, const int* in_sizes, int n_in,
                              void* d_out, int out_size)
{
    const float*     x   = (const float*)d_in[0];
    const void*      ei  = d_in[1];
    const float*     W1  = (const float*)d_in[2];
    const float*     a1s = (const float*)d_in[3];
    const float*     a1d = (const float*)d_in[4];
    const float*     b1  = (const float*)d_in[5];
    const float*     W2  = (const float*)d_in[6];
    const float*     a2s = (const float*)d_in[7];
    const float*     a2d = (const float*)d_in[8];
    const float*     b2  = (const float*)d_in[9];
    const float*     Wn  = (const float*)d_in[10];
    const float*     bn  = (const float*)d_in[11];
    const float*     Wb  = (const float*)d_in[12];
    const float*     bb  = (const float*)d_in[13];
    float* out = (float*)d_out;

    float *xw, *h1, *Y, *ss, *sd, *ex;
    int *r, *c, *cntc, *offc, *curc, *csc_r, *csc_e;
    int *cntr, *offr, *curr, *csr_e;
    cudaGetSymbolAddress((void**)&xw,    g_xw);
    cudaGetSymbolAddress((void**)&h1,    g_h1);
    cudaGetSymbolAddress((void**)&Y,     g_Y);
    cudaGetSymbolAddress((void**)&ss,    g_ss);
    cudaGetSymbolAddress((void**)&sd,    g_sd);
    cudaGetSymbolAddress((void**)&ex,    g_ex);
    cudaGetSymbolAddress((void**)&r,     g_r);
    cudaGetSymbolAddress((void**)&c,     g_c);
    cudaGetSymbolAddress((void**)&cntc,  g_cntc);
    cudaGetSymbolAddress((void**)&offc,  g_offc);
    cudaGetSymbolAddress((void**)&curc,  g_curc);
    cudaGetSymbolAddress((void**)&csc_r, g_csc_r);
    cudaGetSymbolAddress((void**)&csc_e, g_csc_e);
    cudaGetSymbolAddress((void**)&cntr,  g_cntr);
    cudaGetSymbolAddress((void**)&offr,  g_offr);
    cudaGetSymbolAddress((void**)&curr,  g_curr);
    cudaGetSymbolAddress((void**)&csr_e, g_csr_e);

    float* hfin = out + H_OFF;
    float* attn = out + AT_OFF;

    // unconditional every call (idempotent; no static guards allowed)
    cudaFuncSetAttribute(gemm_bf16x3,
                         cudaFuncAttributeMaxDynamicSharedMemorySize, GEMM_SMEM);

    const int TB = 256;
    int gemm_grid = (Nn + 127) / 128;
    int eb  = (ETOT + TB - 1) / TB;
    int e0b = (Ee + TB - 1) / TB;
    int nb  = (Nn + TB - 1) / TB;
    int nwb = (Nn + 7) / 8;

    detect_dtype_kernel<<<1, 32>>>(ei);
    conv_idx_kernel<<<eb, TB>>>(ei, r, c);

    zero_cnt_kernel<<<nb, TB>>>(cntc, cntr);
    hist_kernel<<<eb, TB>>>(c, cntc, ETOT);
    hist_kernel<<<e0b, TB>>>(r, cntr, Ee);
    scan_kernel<<<1, 1024>>>(cntc, offc);
    scan_kernel<<<1, 1024>>>(cntr, offr);
    copy_cur_kernel<<<nb, TB>>>(offc, curc, offr, curr);
    scatter_c_kernel<<<eb, TB>>>(r, c, curc, csc_r, csc_e);
    scatter_r_kernel<<<e0b, TB>>>(r, curr, csr_e);

    // ---------- layer 1 ----------
    gemm_bf16x3<<<gemm_grid, TB, GEMM_SMEM>>>(x, W1, xw, Nn, DD);
    scores_kernel<<<nwb, TB>>>(xw, a1s, a1d, ss, sd);
    gat_fused_kernel<<<nwb, TB>>>(offc, csc_r, csc_e, ss, sd, xw, b1, ex, h1, attn, 0);

    // ---------- layer 2 ----------
    gemm_bf16x3<<<gemm_grid, TB, GEMM_SMEM>>>(h1, W2, xw, Nn, DD);
    scores_kernel<<<nwb, TB>>>(xw, a2s, a2d, ss, sd);
    gat_fused_kernel<<<nwb, TB>>>(offc, csc_r, csc_e, ss, sd, xw, b2, ex, hfin, attn, 1);

    // ---------- heads ----------
    node_pred_kernel<<<nwb, TB>>>(hfin, Wn, bn, out + NP_OFF);
    for (int o = 0; o < 3; o++)
        gemm_bf16x3<<<gemm_grid, TB, GEMM_SMEM>>>(hfin, Wb + (size_t)o * DD * DD,
                                                  Y + o * DD, Nn, 768);
    edge_pred_kernel<<<(Ee + 7) / 8, TB>>>(csr_e, r, c, hfin, Y, bb, out + EP_OFF);
}

// round 13
// speedup vs baseline: 2.0311x; 1.1118x over previous
#include <cuda_runtime.h>
#include <cuda_bf16.h>
#include <math.h>

#define Nn   50000
#define Ee   800000
#define ETOT (Ee + Nn)     // 850000
#define DD   256
#define HH   4
#define NEG  0.2f

// ---- output layout (tuple flatten: node_preds, edge_preds, h, attn_weights) ----
#define NP_OFF  0
#define EP_OFF  (Nn)                    // 50000
#define H_OFF   (Nn + 3*Ee)             // 2450000
#define AT_OFF  (H_OFF + Nn*DD)         // 15250000

// ---- scratch (device globals; no allocation allowed) ----
__device__ float    g_xw [Nn * DD];
__device__ float    g_h1 [Nn * DD];
__device__ float    g_Y  [(size_t)Nn * 768];
__device__ float    g_ss [Nn * HH];
__device__ float    g_sd [Nn * HH];
__device__ float    g_ex [ETOT * HH];      // per-edge exp values (CSC order)
__device__ int      g_r[ETOT];
__device__ int      g_c[ETOT];
__device__ int      g_is64;
// CSC (sorted by target c) over all ETOT edges
__device__ int      g_cntc[Nn];
__device__ int      g_offc[Nn + 1];
__device__ int      g_curc[Nn];
__device__ int      g_csc_r[ETOT];
__device__ int      g_csc_e[ETOT];
// CSR (sorted by source r) over original Ee edges
__device__ int      g_cntr[Nn];
__device__ int      g_offr[Nn + 1];
__device__ int      g_curr[Nn];
__device__ int      g_csr_e[Ee];

// ============================ helpers ============================
__device__ __forceinline__ float lrelu(float x) { return x > 0.f ? x : NEG * x; }

__device__ __forceinline__ unsigned pack_hi2(float a, float b) {
    return __byte_perm(__float_as_uint(a), __float_as_uint(b), 0x7632);
}
__device__ __forceinline__ float resid(float v) {
    return v - __uint_as_float(__float_as_uint(v) & 0xffff0000u);
}
__device__ __forceinline__ unsigned pack_lo2(float a, float b) {
    unsigned d;
    asm("cvt.rn.bf16x2.f32 %0, %1, %2;" : "=r"(d) : "f"(b), "f"(a));
    return d;
}

__device__ __forceinline__ void mma16(float* c, const unsigned* a, const unsigned* b) {
    asm volatile(
        "mma.sync.aligned.m16n8k16.row.col.f32.bf16.bf16.f32 "
        "{%0,%1,%2,%3}, {%4,%5,%6,%7}, {%8,%9}, {%0,%1,%2,%3};"
        : "+f"(c[0]), "+f"(c[1]), "+f"(c[2]), "+f"(c[3])
        : "r"(a[0]), "r"(a[1]), "r"(a[2]), "r"(a[3]), "r"(b[0]), "r"(b[1]));
}

// ============================ index conversion ============================
__global__ void detect_dtype_kernel(const void* pv) {
    if (blockIdx.x == 0 && threadIdx.x == 0) {
        const long long* p64 = (const long long*)pv;
        const int*       p32 = (const int*)pv;
        int ok64 = 1, ok32 = 1;
        for (int i = 0; i < 256; i++) {
            long long v = p64[i];
            if (v < 0 || v >= Nn) ok64 = 0;
            int w = p32[i];
            if (w < 0 || w >= Nn) ok32 = 0;
        }
        g_is64 = ok64 ? 1 : (ok32 ? 0 : 1);
    }
}

__global__ void zero_cnt_kernel(int* a, int* b) {
    int i = blockIdx.x * blockDim.x + threadIdx.x;
    if (i < Nn) { a[i] = 0; b[i] = 0; }
}

// convert + clamp + histogram in one pass
__global__ void conv_idx_hist_kernel(const void* pv, int* r, int* c,
                                     int* cntc, int* cntr) {
    int e = blockIdx.x * blockDim.x + threadIdx.x;
    if (e >= ETOT) return;
    if (e >= Ee) {
        int n = e - Ee;
        r[e] = n; c[e] = n;
        atomicAdd(&cntc[n], 1);
        return;
    }
    int ri, ci;
    if (g_is64) {
        const long long* p = (const long long*)pv;
        ri = (int)p[e]; ci = (int)p[Ee + e];
    } else {
        const int* p = (const int*)pv;
        ri = p[e]; ci = p[Ee + e];
    }
    ri = min(max(ri, 0), Nn - 1);
    ci = min(max(ci, 0), Nn - 1);
    r[e] = ri; c[e] = ci;
    atomicAdd(&cntc[ci], 1);
    atomicAdd(&cntr[ri], 1);
}

__global__ void scan_kernel(const int* __restrict__ cnt, int* __restrict__ off) {
    __shared__ int part[1024];
    const int tid = threadIdx.x;
    const int CH = (Nn + 1023) / 1024;     // 49
    int base = tid * CH;
    int s = 0;
    for (int i = 0; i < CH; i++) {
        int idx = base + i;
        if (idx < Nn) s += cnt[idx];
    }
    part[tid] = s;
    __syncthreads();
    for (int d = 1; d < 1024; d <<= 1) {
        int v = 0;
        if (tid >= d) v = part[tid - d];
        __syncthreads();
        if (tid >= d) part[tid] += v;
        __syncthreads();
    }
    int run = tid ? part[tid - 1] : 0;
    for (int i = 0; i < CH; i++) {
        int idx = base + i;
        if (idx < Nn) { off[idx] = run; run += cnt[idx]; }
    }
    if (tid == 1023) off[Nn] = part[1023];
}

__global__ void copy_cur_kernel(const int* offc, int* curc, const int* offr, int* curr) {
    int i = blockIdx.x * blockDim.x + threadIdx.x;
    if (i < Nn) { curc[i] = offc[i]; curr[i] = offr[i]; }
}

__global__ void scatter_c_kernel(const int* __restrict__ r, const int* __restrict__ c,
                                 int* cur, int* csc_r, int* csc_e) {
    int e = blockIdx.x * blockDim.x + threadIdx.x;
    if (e >= ETOT) return;
    int j = atomicAdd(&cur[c[e]], 1);
    csc_r[j] = r[e];
    csc_e[j] = e;
}

__global__ void scatter_r_kernel(const int* __restrict__ r, int* cur, int* csr_e) {
    int e = blockIdx.x * blockDim.x + threadIdx.x;
    if (e >= Ee) return;
    int j = atomicAdd(&cur[r[e]], 1);
    csr_e[j] = e;
}

// ============================ 3x-bf16 tensor-core GEMM ============================
#define ASTR 132
#define BSTR 260
#define ABUF (16 * ASTR)
#define BBUF (16 * BSTR)
#define GEMM_SMEM ((2 * ABUF + 2 * BBUF) * 4)

__global__ __launch_bounds__(256, 1) void gemm_bf16x3(
    const float* __restrict__ A, const float* __restrict__ B,
    float* __restrict__ C, int M, int ldc)
{
    extern __shared__ float sm[];
    float* Asb = sm;
    float* Bsb = sm + 2 * ABUF;

    const int tid  = threadIdx.x;
    const int wid  = tid >> 5;
    const int lane = tid & 31;
    const int g = lane >> 2, t = lane & 3;
    const int wm = (wid & 1) * 64;
    const int wn = (wid >> 1) * 64;
    const int bm = blockIdx.x * 128;

    const int arow = tid >> 1;
    const int acol = (tid & 1) * 8;
    const int brow = tid >> 4;
    const int bcol = (tid & 15) * 16;

    float4 ra0, ra1, rb[4];
    {
        int r0 = bm + arow;
        if (r0 < M) {
            ra0 = *(const float4*)(A + (size_t)r0 * 256 + acol);
            ra1 = *(const float4*)(A + (size_t)r0 * 256 + acol + 4);
        } else { ra0 = make_float4(0,0,0,0); ra1 = ra0; }
#pragma unroll
        for (int q = 0; q < 4; q++)
            rb[q] = *(const float4*)(B + (size_t)brow * 256 + bcol + q * 4);
    }
    {
        float* As = Asb;
        As[(acol+0)*ASTR + arow] = ra0.x; As[(acol+1)*ASTR + arow] = ra0.y;
        As[(acol+2)*ASTR + arow] = ra0.z; As[(acol+3)*ASTR + arow] = ra0.w;
        As[(acol+4)*ASTR + arow] = ra1.x; As[(acol+5)*ASTR + arow] = ra1.y;
        As[(acol+6)*ASTR + arow] = ra1.z; As[(acol+7)*ASTR + arow] = ra1.w;
        float* Bsr = Bsb + brow * BSTR;
#pragma unroll
        for (int q = 0; q < 4; q++)
            *(float4*)(Bsr + bcol + q * 4) = rb[q];
    }
    __syncthreads();

    float acc[4][8][4];
#pragma unroll
    for (int mi = 0; mi < 4; mi++)
#pragma unroll
        for (int ni = 0; ni < 8; ni++)
#pragma unroll
            for (int q = 0; q < 4; q++) acc[mi][ni][q] = 0.f;

    for (int ki = 0; ki < 16; ki++) {
        const int buf = ki & 1;
        if (ki < 15) {
            int k0 = (ki + 1) * 16;
            int r0 = bm + arow;
            if (r0 < M) {
                ra0 = *(const float4*)(A + (size_t)r0 * 256 + k0 + acol);
                ra1 = *(const float4*)(A + (size_t)r0 * 256 + k0 + acol + 4);
            } else { ra0 = make_float4(0,0,0,0); ra1 = ra0; }
#pragma unroll
            for (int q = 0; q < 4; q++)
                rb[q] = *(const float4*)(B + (size_t)(k0 + brow) * 256 + bcol + q * 4);
        }

        const float* As = Asb + buf * ABUF;
        const float* Bs = Bsb + buf * BBUF;

        unsigned ahi[4][4], alo[4][4], bhi[8][2], blo[8][2];
#pragma unroll
        for (int mi = 0; mi < 4; mi++) {
            int r0 = wm + mi * 16 + g;
            float v00 = As[(2*t  )*ASTR + r0], v01 = As[(2*t+1)*ASTR + r0];
            float v10 = As[(2*t  )*ASTR + r0+8], v11 = As[(2*t+1)*ASTR + r0+8];
            float v20 = As[(2*t+8)*ASTR + r0], v21 = As[(2*t+9)*ASTR + r0];
            float v30 = As[(2*t+8)*ASTR + r0+8], v31 = As[(2*t+9)*ASTR + r0+8];
            ahi[mi][0] = pack_hi2(v00, v01); alo[mi][0] = pack_lo2(resid(v00), resid(v01));
            ahi[mi][1] = pack_hi2(v10, v11); alo[mi][1] = pack_lo2(resid(v10), resid(v11));
            ahi[mi][2] = pack_hi2(v20, v21); alo[mi][2] = pack_lo2(resid(v20), resid(v21));
            ahi[mi][3] = pack_hi2(v30, v31); alo[mi][3] = pack_lo2(resid(v30), resid(v31));
        }
#pragma unroll
        for (int ni = 0; ni < 8; ni++) {
            int c0 = wn + ni * 8 + g;
            float w00 = Bs[(2*t  )*BSTR + c0], w01 = Bs[(2*t+1)*BSTR + c0];
            float w10 = Bs[(2*t+8)*BSTR + c0], w11 = Bs[(2*t+9)*BSTR + c0];
            bhi[ni][0] = pack_hi2(w00, w01); blo[ni][0] = pack_lo2(resid(w00), resid(w01));
            bhi[ni][1] = pack_hi2(w10, w11); blo[ni][1] = pack_lo2(resid(w10), resid(w11));
        }
#pragma unroll
        for (int mi = 0; mi < 4; mi++)
#pragma unroll
            for (int ni = 0; ni < 8; ni++) {
                mma16(acc[mi][ni], alo[mi], bhi[ni]);
                mma16(acc[mi][ni], ahi[mi], blo[ni]);
                mma16(acc[mi][ni], ahi[mi], bhi[ni]);
            }

        if (ki < 15) {
            const int nb = buf ^ 1;
            float* Asn = Asb + nb * ABUF;
            Asn[(acol+0)*ASTR + arow] = ra0.x; Asn[(acol+1)*ASTR + arow] = ra0.y;
            Asn[(acol+2)*ASTR + arow] = ra0.z; Asn[(acol+3)*ASTR + arow] = ra0.w;
            Asn[(acol+4)*ASTR + arow] = ra1.x; Asn[(acol+5)*ASTR + arow] = ra1.y;
            Asn[(acol+6)*ASTR + arow] = ra1.z; Asn[(acol+7)*ASTR + arow] = ra1.w;
            float* Bsn = Bsb + nb * BBUF + brow * BSTR;
#pragma unroll
            for (int q = 0; q < 4; q++)
                *(float4*)(Bsn + bcol + q * 4) = rb[q];
            __syncthreads();
        }
    }

#pragma unroll
    for (int mi = 0; mi < 4; mi++) {
        int row0 = bm + wm + mi * 16 + g;
        int row1 = row0 + 8;
#pragma unroll
        for (int ni = 0; ni < 8; ni++) {
            int col = wn + ni * 8 + 2 * t;
            if (row0 < M)
                *(float2*)(C + (size_t)row0 * ldc + col) =
                    make_float2(acc[mi][ni][0], acc[mi][ni][1]);
            if (row1 < M)
                *(float2*)(C + (size_t)row1 * ldc + col) =
                    make_float2(acc[mi][ni][2], acc[mi][ni][3]);
        }
    }
}

// ============================ attention scores ============================
__global__ void scores_kernel(const float* __restrict__ xw,
                              const float* __restrict__ a_src,
                              const float* __restrict__ a_dst,
                              float* __restrict__ s_src,
                              float* __restrict__ s_dst)
{
    int w = (blockIdx.x * blockDim.x + threadIdx.x) >> 5;
    int lane = threadIdx.x & 31;
    if (w >= Nn) return;
    const float4* xp  = (const float4*)(xw + (size_t)w * DD);
    const float4* asp = (const float4*)a_src;
    const float4* adp = (const float4*)a_dst;
    float ps = 0.f, pd = 0.f;
#pragma unroll
    for (int q = 0; q < 2; q++) {
        int i = lane * 2 + q;
        float4 x4 = xp[i];
        float4 s4 = asp[i], d4 = adp[i];
        ps += x4.x * s4.x + x4.y * s4.y + x4.z * s4.z + x4.w * s4.w;
        pd += x4.x * d4.x + x4.y * d4.y + x4.z * d4.z + x4.w * d4.w;
    }
#pragma unroll
    for (int off = 4; off; off >>= 1) {
        ps += __shfl_down_sync(0xffffffffu, ps, off);
        pd += __shfl_down_sync(0xffffffffu, pd, off);
    }
    if ((lane & 7) == 0) {
        int h = lane >> 3;
        s_src[w * HH + h] = ps;
        s_dst[w * HH + h] = pd;
    }
}

// ============================ fused GAT layer (warp per node) ============================
__global__ __launch_bounds__(256) void gat_fused_kernel(
    const int* __restrict__ off, const int* __restrict__ csc_r,
    const int* __restrict__ csc_e,
    const float* __restrict__ s_src, const float* __restrict__ s_dst,
    const float* __restrict__ xw, const float* __restrict__ bias,
    float* __restrict__ ex, float* __restrict__ outh,
    float* __restrict__ attn, int accumulate)
{
    const int n = (blockIdx.x * blockDim.x + threadIdx.x) >> 5;
    const int lane = threadIdx.x & 31;
    if (n >= Nn) return;

    const int beg = off[n], end = off[n + 1];
    const float4 sd4 = *(const float4*)(s_dst + (size_t)n * HH);

    float4 mx = make_float4(-1e30f, -1e30f, -1e30f, -1e30f);
    for (int j = beg + lane; j < end; j += 32) {
        int ri = csc_r[j];
        float4 ss = *(const float4*)(s_src + (size_t)ri * HH);
        mx.x = fmaxf(mx.x, lrelu(ss.x + sd4.x));
        mx.y = fmaxf(mx.y, lrelu(ss.y + sd4.y));
        mx.z = fmaxf(mx.z, lrelu(ss.z + sd4.z));
        mx.w = fmaxf(mx.w, lrelu(ss.w + sd4.w));
    }
#pragma unroll
    for (int o = 16; o; o >>= 1) {
        mx.x = fmaxf(mx.x, __shfl_xor_sync(0xffffffffu, mx.x, o));
        mx.y = fmaxf(mx.y, __shfl_xor_sync(0xffffffffu, mx.y, o));
        mx.z = fmaxf(mx.z, __shfl_xor_sync(0xffffffffu, mx.z, o));
        mx.w = fmaxf(mx.w, __shfl_xor_sync(0xffffffffu, mx.w, o));
    }

    float4 den = make_float4(0.f, 0.f, 0.f, 0.f);
    for (int j = beg + lane; j < end; j += 32) {
        int ri = csc_r[j];
        float4 ss = *(const float4*)(s_src + (size_t)ri * HH);
        float4 v;
        v.x = expf(lrelu(ss.x + sd4.x) - mx.x);
        v.y = expf(lrelu(ss.y + sd4.y) - mx.y);
        v.z = expf(lrelu(ss.z + sd4.z) - mx.z);
        v.w = expf(lrelu(ss.w + sd4.w) - mx.w);
        *(float4*)(ex + (size_t)j * HH) = v;
        den.x += v.x; den.y += v.y; den.z += v.z; den.w += v.w;
    }
#pragma unroll
    for (int o = 16; o; o >>= 1) {
        den.x += __shfl_xor_sync(0xffffffffu, den.x, o);
        den.y += __shfl_xor_sync(0xffffffffu, den.y, o);
        den.z += __shfl_xor_sync(0xffffffffu, den.z, o);
        den.w += __shfl_xor_sync(0xffffffffu, den.w, o);
    }
    const float4 inv = make_float4(1.f / den.x, 1.f / den.y, 1.f / den.z, 1.f / den.w);
    __syncwarp();

    for (int j = beg + lane; j < end; j += 32) {
        float4 v = *(const float4*)(ex + (size_t)j * HH);
        float s = 0.125f * (v.x * inv.x + v.y * inv.y + v.z * inv.z + v.w * inv.w);
        int oe = csc_e[j];
        if (accumulate) attn[oe] += s; else attn[oe] = s;
    }

    const int h = lane >> 3;
    const float invh = (h == 0) ? inv.x : (h == 1) ? inv.y : (h == 2) ? inv.z : inv.w;
    const int col = lane * 8;

    const float4* b4 = (const float4*)(bias);
    float4 a0 = b4[lane * 2], a1 = b4[lane * 2 + 1];

    int j = beg;
    for (; j + 1 < end; j += 2) {
        int ri0 = csc_r[j], ri1 = csc_r[j + 1];
        float e0 = ex[(size_t)j * HH + h];
        float e1 = ex[(size_t)(j + 1) * HH + h];
        const float4* xp0 = (const float4*)(xw + (size_t)ri0 * DD + col);
        const float4* xp1 = (const float4*)(xw + (size_t)ri1 * DD + col);
        float4 u0 = xp0[0], u1 = xp0[1];
        float4 w0 = xp1[0], w1 = xp1[1];
        float al0 = e0 * invh, al1 = e1 * invh;
        a0.x += al0 * u0.x; a0.y += al0 * u0.y; a0.z += al0 * u0.z; a0.w += al0 * u0.w;
        a1.x += al0 * u1.x; a1.y += al0 * u1.y; a1.z += al0 * u1.z; a1.w += al0 * u1.w;
        a0.x += al1 * w0.x; a0.y += al1 * w0.y; a0.z += al1 * w0.z; a0.w += al1 * w0.w;
        a1.x += al1 * w1.x; a1.y += al1 * w1.y; a1.z += al1 * w1.z; a1.w += al1 * w1.w;
    }
    if (j < end) {
        int ri = csc_r[j];
        float alpha = ex[(size_t)j * HH + h] * invh;
        const float4* xp = (const float4*)(xw + (size_t)ri * DD + col);
        float4 v0 = xp[0], v1 = xp[1];
        a0.x += alpha * v0.x; a0.y += alpha * v0.y;
        a0.z += alpha * v0.z; a0.w += alpha * v0.w;
        a1.x += alpha * v1.x; a1.y += alpha * v1.y;
        a1.z += alpha * v1.z; a1.w += alpha * v1.w;
    }

    a0.x = a0.x > 0.f ? a0.x : expf(a0.x) - 1.f;
    a0.y = a0.y > 0.f ? a0.y : expf(a0.y) - 1.f;
    a0.z = a0.z > 0.f ? a0.z : expf(a0.z) - 1.f;
    a0.w = a0.w > 0.f ? a0.w : expf(a0.w) - 1.f;
    a1.x = a1.x > 0.f ? a1.x : expf(a1.x) - 1.f;
    a1.y = a1.y > 0.f ? a1.y : expf(a1.y) - 1.f;
    a1.z = a1.z > 0.f ? a1.z : expf(a1.z) - 1.f;
    a1.w = a1.w > 0.f ? a1.w : expf(a1.w) - 1.f;
    float4* op = (float4*)(outh + (size_t)n * DD + col);
    op[0] = a0; op[1] = a1;
}

// ============================ prediction heads ============================
__global__ void node_pred_kernel(const float* __restrict__ h, const float* __restrict__ Wn,
                                 const float* __restrict__ bn, float* __restrict__ out)
{
    int n = (blockIdx.x * blockDim.x + threadIdx.x) >> 5;
    int lane = threadIdx.x & 31;
    if (n >= Nn) return;
    const float4* hp = (const float4*)(h + (size_t)n * DD);
    const float4* wp = (const float4*)Wn;
    float s = 0.f;
#pragma unroll
    for (int q = 0; q < 2; q++) {
        int i = lane * 2 + q;
        float4 a = hp[i], b = wp[i];
        s += a.x * b.x + a.y * b.y + a.z * b.z + a.w * b.w;
    }
#pragma unroll
    for (int off = 16; off; off >>= 1) s += __shfl_down_sync(0xffffffffu, s, off);
    if (lane == 0) out[n] = s + bn[0];
}

// warp per source node: Y row held in registers across all out-edges
__global__ void edge_pred_csr_kernel(const int* __restrict__ offr,
                                     const int* __restrict__ csr_e,
                                     const int* __restrict__ c,
                                     const float* __restrict__ h,
                                     const float* __restrict__ Y,
                                     const float* __restrict__ bb,
                                     float* __restrict__ out)
{
    int n = (blockIdx.x * blockDim.x + threadIdx.x) >> 5;
    int lane = threadIdx.x & 31;
    if (n >= Nn) return;
    int beg = offr[n], end = offr[n + 1];
    if (beg == end) return;

    float4 y[3][2];
#pragma unroll
    for (int o = 0; o < 3; o++) {
        const float4* yp = (const float4*)(Y + (size_t)n * 768 + o * DD);
        y[o][0] = yp[lane * 2];
        y[o][1] = yp[lane * 2 + 1];
    }
    float bb0 = bb[0], bb1 = bb[1], bb2 = bb[2];

    for (int j = beg; j < end; j++) {
        int oe = csr_e[j];
        int ci = c[oe];
        const float4* hp = (const float4*)(h + (size_t)ci * DD);
        float4 h0 = hp[lane * 2], h1 = hp[lane * 2 + 1];
        float s0, s1, s2;
        s0 = h0.x*y[0][0].x + h0.y*y[0][0].y + h0.z*y[0][0].z + h0.w*y[0][0].w
           + h1.x*y[0][1].x + h1.y*y[0][1].y + h1.z*y[0][1].z + h1.w*y[0][1].w;
        s1 = h0.x*y[1][0].x + h0.y*y[1][0].y + h0.z*y[1][0].z + h0.w*y[1][0].w
           + h1.x*y[1][1].x + h1.y*y[1][1].y + h1.z*y[1][1].z + h1.w*y[1][1].w;
        s2 = h0.x*y[2][0].x + h0.y*y[2][0].y + h0.z*y[2][0].z + h0.w*y[2][0].w
           + h1.x*y[2][1].x + h1.y*y[2][1].y + h1.z*y[2][1].z + h1.w*y[2][1].w;
#pragma unroll
        for (int off = 16; off; off >>= 1) {
            s0 += __shfl_down_sync(0xffffffffu, s0, off);
            s1 += __shfl_down_sync(0xffffffffu, s1, off);
            s2 += __shfl_down_sync(0xffffffffu, s2, off);
        }
        if (lane == 0) {
            float* op = out + (size_t)oe * 3;
            op[0] = s0 + bb0;
            op[1] = s1 + bb1;
            op[2] = s2 + bb2;
        }
    }
}

// ============================ host launch ============================
extern "C" void kernel_launch(void* const* d_in, const int* in_sizes, int n_in,
                              void* d_out, int out_size)
{
    const float*     x   = (const float*)d_in[0];
    const void*      ei  = d_in[1];
    const float*     W1  = (const float*)d_in[2];
    const float*     a1s = (const float*)d_in[3];
    const float*     a1d = (const float*)d_in[4];
    const float*     b1  = (const float*)d_in[5];
    const float*     W2  = (const float*)d_in[6];
    const float*     a2s = (const float*)d_in[7];
    const float*     a2d = (const float*)d_in[8];
    const float*     b2  = (const float*)d_in[9];
    const float*     Wn  = (const float*)d_in[10];
    const float*     bn  = (const float*)d_in[11];
    const float*     Wb  = (const float*)d_in[12];
    const float*     bb  = (const float*)d_in[13];
    float* out = (float*)d_out;

    float *xw, *h1, *Y, *ss, *sd, *ex;
    int *r, *c, *cntc, *offc, *curc, *csc_r, *csc_e;
    int *cntr, *offr, *curr, *csr_e;
    cudaGetSymbolAddress((void**)&xw,    g_xw);
    cudaGetSymbolAddress((void**)&h1,    g_h1);
    cudaGetSymbolAddress((void**)&Y,     g_Y);
    cudaGetSymbolAddress((void**)&ss,    g_ss);
    cudaGetSymbolAddress((void**)&sd,    g_sd);
    cudaGetSymbolAddress((void**)&ex,    g_ex);
    cudaGetSymbolAddress((void**)&r,     g_r);
    cudaGetSymbolAddress((void**)&c,     g_c);
    cudaGetSymbolAddress((void**)&cntc,  g_cntc);
    cudaGetSymbolAddress((void**)&offc,  g_offc);
    cudaGetSymbolAddress((void**)&curc,  g_curc);
    cudaGetSymbolAddress((void**)&csc_r, g_csc_r);
    cudaGetSymbolAddress((void**)&csc_e, g_csc_e);
    cudaGetSymbolAddress((void**)&cntr,  g_cntr);
    cudaGetSymbolAddress((void**)&offr,  g_offr);
    cudaGetSymbolAddress((void**)&curr,  g_curr);
    cudaGetSymbolAddress((void**)&csr_e, g_csr_e);

    float* hfin = out + H_OFF;
    float* attn = out + AT_OFF;

    cudaFuncSetAttribute(gemm_bf16x3,
                         cudaFuncAttributeMaxDynamicSharedMemorySize, GEMM_SMEM);

    const int TB = 256;
    int gemm_grid = (Nn + 127) / 128;
    int eb  = (ETOT + TB - 1) / TB;
    int e0b = (Ee + TB - 1) / TB;
    int nb  = (Nn + TB - 1) / TB;
    int nwb = (Nn + 7) / 8;

    detect_dtype_kernel<<<1, 32>>>(ei);
    zero_cnt_kernel<<<nb, TB>>>(cntc, cntr);
    conv_idx_hist_kernel<<<eb, TB>>>(ei, r, c, cntc, cntr);
    scan_kernel<<<1, 1024>>>(cntc, offc);
    scan_kernel<<<1, 1024>>>(cntr, offr);
    copy_cur_kernel<<<nb, TB>>>(offc, curc, offr, curr);
    scatter_c_kernel<<<eb, TB>>>(r, c, curc, csc_r, csc_e);
    scatter_r_kernel<<<e0b, TB>>>(r, curr, csr_e);

    // ---------- layer 1 ----------
    gemm_bf16x3<<<gemm_grid, TB, GEMM_SMEM>>>(x, W1, xw, Nn, DD);
    scores_kernel<<<nwb, TB>>>(xw, a1s, a1d, ss, sd);
    gat_fused_kernel<<<nwb, TB>>>(offc, csc_r, csc_e, ss, sd, xw, b1, ex, h1, attn, 0);

    // ---------- layer 2 ----------
    gemm_bf16x3<<<gemm_grid, TB, GEMM_SMEM>>>(h1, W2, xw, Nn, DD);
    scores_kernel<<<nwb, TB>>>(xw, a2s, a2d, ss, sd);
    gat_fused_kernel<<<nwb, TB>>>(offc, csc_r, csc_e, ss, sd, xw, b2, ex, hfin, attn, 1);

    // ---------- heads ----------
    node_pred_kernel<<<nwb, TB>>>(hfin, Wn, bn, out + NP_OFF);
    for (int o = 0; o < 3; o++)
        gemm_bf16x3<<<gemm_grid, TB, GEMM_SMEM>>>(hfin, Wb + (size_t)o * DD * DD,
                                                  Y + o * DD, Nn, 768);
    edge_pred_csr_kernel<<<nwb, TB>>>(offr, csr_e, c, hfin, Y, bb, out + EP_OFF);
}